// round 1
// baseline (speedup 1.0000x reference)
#include <cuda_runtime.h>
#include <cstdint>

// ---------------------------------------------------------------------------
// NodeBernNet: h=relu(xW); Tx1..3 = L^k h (COO spmm); poly_f = sum_k coef[f,k] Tx_k
// (coef = thetas @ BCOEF); concat-attention over F=2; 3-layer MLP head.
// Fixed shapes: N=100000, E=1600000, C_IN=128, C=64, F=2, K+1=4, NUM_CLASS=2.
// ---------------------------------------------------------------------------

#define NMAX 100000
#define CDIM 64

// Scratch (static device globals: allocation-free, graph-capture safe)
__device__ __align__(256) float g_h   [NMAX * CDIM];
__device__ __align__(256) float g_T1  [NMAX * CDIM];
__device__ __align__(256) float g_T2  [NMAX * CDIM];
__device__ __align__(256) float g_T3  [NMAX * CDIM];
__device__ __align__(256) float g_poly [2 * NMAX * CDIM];
__device__ __align__(256) float g_polyb[2 * NMAX * CDIM];
__device__ __align__(256) float g_xproj[NMAX * CDIM];
__device__ __align__(256) float g_res  [NMAX * CDIM];
__device__ __align__(256) float g_y1   [NMAX * CDIM];
__device__ __align__(256) float g_y2   [NMAX * 32];
__device__ float g_coef[8];   // [F=2][K+1=4], coef = thetas @ BCOEF
__device__ int   g_is64;      // edge index dtype: 1 if int64, 0 if int32

// ---------------------------------------------------------------------------
// Prep: detect edge index width; fold BCOEF into thetas.
// int64 detection: values are in [0, 100000); for little-endian int64 the
// odd 32-bit words are always 0. P(4 random int32 indices all == 0) ~ 0.
// ---------------------------------------------------------------------------
__global__ void prep_kernel(const void* __restrict__ esrc,
                            const float* __restrict__ thetas)
{
    if (threadIdx.x == 0) {
        const int* w = (const int*)esrc;
        g_is64 = (w[1] == 0 && w[3] == 0 && w[5] == 0 && w[7] == 0) ? 1 : 0;
        const float B[4][4] = {
            {1.f, -3.f,  3.f, -1.f},
            {0.f,  3.f, -6.f,  3.f},
            {0.f,  0.f,  3.f, -3.f},
            {0.f,  0.f,  0.f,  1.f}};
        for (int f = 0; f < 2; f++)
            for (int k = 0; k < 4; k++) {
                float s = 0.f;
                for (int j = 0; j < 4; j++) s += thetas[f * 4 + j] * B[j][k];
                g_coef[f * 4 + k] = s;
            }
    }
}

// ---------------------------------------------------------------------------
// Tiled SIMT GEMM: C[M,Nout] = act(A[M,K] @ W[K,Nout] + bias), act: 0=none,1=relu
// BM=64, BN=64, BK=16, 256 threads, 4x4 per-thread microtile.
// ---------------------------------------------------------------------------
__global__ void gemm_bias_act(const float* __restrict__ A,
                              const float* __restrict__ W,
                              const float* __restrict__ bias,
                              float* __restrict__ C,
                              int M, int K, int Nout, int act)
{
    __shared__ float As[16][68];   // [k][m], padded
    __shared__ float Bs[16][68];   // [k][n], padded

    const int tx = threadIdx.x & 15;   // n tile coord
    const int ty = threadIdx.x >> 4;   // m tile coord
    const int m0 = blockIdx.x * 64;

    float acc[4][4] = {};

    for (int k0 = 0; k0 < K; k0 += 16) {
        #pragma unroll
        for (int r = 0; r < 4; r++) {
            int i = threadIdx.x + r * 256;        // 0..1023
            int m = i >> 4, k = i & 15;
            int gm = m0 + m;
            float v = 0.f;
            if (gm < M) v = A[(size_t)gm * K + k0 + k];
            As[k][m] = v;
        }
        #pragma unroll
        for (int r = 0; r < 4; r++) {
            int i = threadIdx.x + r * 256;
            int k = i >> 6, n = i & 63;
            float v = 0.f;
            if (n < Nout) v = W[(size_t)(k0 + k) * Nout + n];
            Bs[k][n] = v;
        }
        __syncthreads();
        #pragma unroll
        for (int kk = 0; kk < 16; kk++) {
            float a[4], b[4];
            #pragma unroll
            for (int i = 0; i < 4; i++) a[i] = As[kk][ty * 4 + i];
            #pragma unroll
            for (int j = 0; j < 4; j++) b[j] = Bs[kk][tx * 4 + j];
            #pragma unroll
            for (int i = 0; i < 4; i++)
                #pragma unroll
                for (int j = 0; j < 4; j++)
                    acc[i][j] += a[i] * b[j];
        }
        __syncthreads();
    }

    #pragma unroll
    for (int i = 0; i < 4; i++) {
        int gm = m0 + ty * 4 + i;
        if (gm >= M) continue;
        #pragma unroll
        for (int j = 0; j < 4; j++) {
            int n = tx * 4 + j;
            if (n < Nout) {
                float v = acc[i][j] + bias[n];
                if (act) v = fmaxf(v, 0.f);
                C[(size_t)gm * Nout + n] = v;
            }
        }
    }
}

// ---------------------------------------------------------------------------
// SpMM: out[dst] += val * h[src], edge-parallel, vectorized float4 reductions.
// 16 lanes per edge (each lane covers 4 of the 64 channels).
// ---------------------------------------------------------------------------
__global__ void spmm_kernel(const void* __restrict__ esrc,
                            const void* __restrict__ edst,
                            const float* __restrict__ ev,
                            const float* __restrict__ hin,
                            float* __restrict__ hout,
                            int E)
{
    int t = blockIdx.x * blockDim.x + threadIdx.x;
    int lane = t & 31;
    int warp = t >> 5;
    int e = warp * 2 + (lane >> 4);
    if (e >= E) return;
    int j = lane & 15;

    int src, dst;
    if (g_is64) {
        src = (int)((const long long*)esrc)[e];
        dst = (int)((const long long*)edst)[e];
    } else {
        src = ((const int*)esrc)[e];
        dst = ((const int*)edst)[e];
    }
    float val = ev[e];
    float4 v = *((const float4*)(hin + (size_t)src * CDIM) + j);
    float* o = (float*)((float4*)(hout + (size_t)dst * CDIM) + j);
    asm volatile("red.relaxed.gpu.global.add.v4.f32 [%0], {%1,%2,%3,%4};"
                 :: "l"(o), "f"(v.x * val), "f"(v.y * val),
                    "f"(v.z * val), "f"(v.w * val)
                 : "memory");
}

// ---------------------------------------------------------------------------
// poly[n,f,c] = sum_k coef[f,k] * Tx_k[n,c], float4-vectorized.
// ---------------------------------------------------------------------------
__global__ void poly_kernel(const float* __restrict__ h,
                            const float* __restrict__ t1,
                            const float* __restrict__ t2,
                            const float* __restrict__ t3,
                            float* __restrict__ poly,
                            int nn)
{
    int idx = blockIdx.x * blockDim.x + threadIdx.x;   // over nn*16 float4s
    if (idx >= nn * 16) return;
    int n = idx >> 4;
    int q = idx & 15;

    float4 a = ((const float4*)h)[idx];
    float4 b = ((const float4*)t1)[idx];
    float4 c = ((const float4*)t2)[idx];
    float4 d = ((const float4*)t3)[idx];

    float c00 = g_coef[0], c01 = g_coef[1], c02 = g_coef[2], c03 = g_coef[3];
    float c10 = g_coef[4], c11 = g_coef[5], c12 = g_coef[6], c13 = g_coef[7];

    float4 p0, p1;
    p0.x = c00*a.x + c01*b.x + c02*c.x + c03*d.x;
    p0.y = c00*a.y + c01*b.y + c02*c.y + c03*d.y;
    p0.z = c00*a.z + c01*b.z + c02*c.z + c03*d.z;
    p0.w = c00*a.w + c01*b.w + c02*c.w + c03*d.w;
    p1.x = c10*a.x + c11*b.x + c12*c.x + c13*d.x;
    p1.y = c10*a.y + c11*b.y + c12*c.y + c13*d.y;
    p1.z = c10*a.z + c11*b.z + c12*c.z + c13*d.z;
    p1.w = c10*a.w + c11*b.w + c12*c.w + c13*d.w;

    ((float4*)poly)[(size_t)n * 32 + q]      = p0;   // (n*2+0)*16 + q
    ((float4*)poly)[(size_t)n * 32 + 16 + q] = p1;   // (n*2+1)*16 + q
}

// ---------------------------------------------------------------------------
// Attention: score_f = sum_c tanh(polyb[n,f,c] + xproj[n,c]) * vc[c];
// softmax over F=2; res[n,c] = a0*poly[n,0,c] + a1*poly[n,1,c].
// One warp per node; lane owns channels {lane, lane+32}.
// ---------------------------------------------------------------------------
__global__ void attn_kernel(const float* __restrict__ poly,
                            const float* __restrict__ polyb,
                            const float* __restrict__ xproj,
                            const float* __restrict__ vc,
                            float* __restrict__ res,
                            int nn)
{
    int gw = (blockIdx.x * blockDim.x + threadIdx.x) >> 5;
    int lane = threadIdx.x & 31;
    if (gw >= nn) return;

    size_t nb = (size_t)gw * CDIM;
    float xp0 = xproj[nb + lane];
    float xp1 = xproj[nb + lane + 32];
    float vc0 = vc[lane];
    float vc1 = vc[lane + 32];

    float s[2];
    #pragma unroll
    for (int f = 0; f < 2; f++) {
        size_t pb = ((size_t)gw * 2 + f) * CDIM;
        float t0 = tanhf(polyb[pb + lane] + xp0);
        float t1 = tanhf(polyb[pb + lane + 32] + xp1);
        float p = t0 * vc0 + t1 * vc1;
        #pragma unroll
        for (int o = 16; o > 0; o >>= 1)
            p += __shfl_xor_sync(0xffffffffu, p, o);
        s[f] = p;
    }
    float m  = fmaxf(s[0], s[1]);
    float e0 = expf(s[0] - m), e1 = expf(s[1] - m);
    float inv = 1.f / (e0 + e1);
    float a0 = e0 * inv, a1 = e1 * inv;

    size_t p0 = (size_t)gw * 2 * CDIM;
    size_t p1 = p0 + CDIM;
    res[nb + lane]      = a0 * poly[p0 + lane]      + a1 * poly[p1 + lane];
    res[nb + lane + 32] = a0 * poly[p0 + lane + 32] + a1 * poly[p1 + lane + 32];
}

// ---------------------------------------------------------------------------
// Head: out[n,0:2] = y2[n,0:32] @ W3[32,2] + b3. One thread per node.
// ---------------------------------------------------------------------------
__global__ void head_kernel(const float* __restrict__ y2,
                            const float* __restrict__ W3,
                            const float* __restrict__ b3,
                            float* __restrict__ out,
                            int nn)
{
    int n = blockIdx.x * blockDim.x + threadIdx.x;
    if (n >= nn) return;
    float s0 = b3[0], s1 = b3[1];
    const float* row = y2 + (size_t)n * 32;
    #pragma unroll
    for (int c = 0; c < 32; c++) {
        float v = row[c];
        s0 += v * W3[c * 2];
        s1 += v * W3[c * 2 + 1];
    }
    out[n * 2]     = s0;
    out[n * 2 + 1] = s1;
}

// ---------------------------------------------------------------------------
extern "C" void kernel_launch(void* const* d_in, const int* in_sizes, int n_in,
                              void* d_out, int out_size)
{
    const float* x      = (const float*)d_in[0];
    const void*  esrc   = d_in[1];
    const void*  edst   = d_in[2];
    const float* ev     = (const float*)d_in[3];
    const float* Win    = (const float*)d_in[4];
    const float* bin    = (const float*)d_in[5];
    const float* thetas = (const float*)d_in[6];
    const float* Wb     = (const float*)d_in[7];
    const float* bWb    = (const float*)d_in[8];
    const float* Wx     = (const float*)d_in[9];
    const float* bWx    = (const float*)d_in[10];
    const float* vc     = (const float*)d_in[11];
    const float* W1     = (const float*)d_in[12];
    const float* b1     = (const float*)d_in[13];
    const float* W2     = (const float*)d_in[14];
    const float* b2     = (const float*)d_in[15];
    const float* W3     = (const float*)d_in[16];
    const float* b3     = (const float*)d_in[17];

    int n = in_sizes[0] / 128;   // number of nodes
    int E = in_sizes[3];         // edge_vals count (float -> exact E)

    float *ph, *pT1, *pT2, *pT3, *ppoly, *ppolyb, *pxp, *pres, *py1, *py2;
    cudaGetSymbolAddress((void**)&ph,     g_h);
    cudaGetSymbolAddress((void**)&pT1,    g_T1);
    cudaGetSymbolAddress((void**)&pT2,    g_T2);
    cudaGetSymbolAddress((void**)&pT3,    g_T3);
    cudaGetSymbolAddress((void**)&ppoly,  g_poly);
    cudaGetSymbolAddress((void**)&ppolyb, g_polyb);
    cudaGetSymbolAddress((void**)&pxp,    g_xproj);
    cudaGetSymbolAddress((void**)&pres,   g_res);
    cudaGetSymbolAddress((void**)&py1,    g_y1);
    cudaGetSymbolAddress((void**)&py2,    g_y2);

    size_t rowBytes = (size_t)n * CDIM * sizeof(float);

    prep_kernel<<<1, 32>>>(esrc, thetas);

    // h = relu(x @ W_in + b_in)
    gemm_bias_act<<<(n + 63) / 64, 256>>>(x, Win, bin, ph, n, 128, 64, 1);

    // Tx1..Tx3 via edge-parallel spmm
    int spmm_blocks = (((E + 1) / 2) * 32 + 255) / 256;
    cudaMemsetAsync(pT1, 0, rowBytes, 0);
    spmm_kernel<<<spmm_blocks, 256>>>(esrc, edst, ev, ph,  pT1, E);
    cudaMemsetAsync(pT2, 0, rowBytes, 0);
    spmm_kernel<<<spmm_blocks, 256>>>(esrc, edst, ev, pT1, pT2, E);
    cudaMemsetAsync(pT3, 0, rowBytes, 0);
    spmm_kernel<<<spmm_blocks, 256>>>(esrc, edst, ev, pT2, pT3, E);

    // poly[n,f,c]
    poly_kernel<<<(n * 16 + 255) / 256, 256>>>(ph, pT1, pT2, pT3, ppoly, n);

    // attention projections
    gemm_bias_act<<<(2 * n + 63) / 64, 256>>>(ppoly, Wb, bWb, ppolyb, 2 * n, 64, 64, 0);
    gemm_bias_act<<<(n + 63) / 64, 256>>>(ph, Wx, bWx, pxp, n, 64, 64, 0);

    attn_kernel<<<(n * 32 + 127) / 128, 128>>>(ppoly, ppolyb, pxp, vc, pres, n);

    // classifier head
    gemm_bias_act<<<(n + 63) / 64, 256>>>(pres, W1, b1, py1, n, 64, 64, 1);
    gemm_bias_act<<<(n + 63) / 64, 256>>>(py1, W2, b2, py2, n, 64, 32, 1);
    head_kernel<<<(n + 255) / 256, 256>>>(py2, W3, b3, (float*)d_out, n);
}

// round 2
// speedup vs baseline: 1.5955x; 1.5955x over previous
#include <cuda_runtime.h>
#include <cstdint>

// ---------------------------------------------------------------------------
// NodeBernNet fixed shapes: N=100000, E=1600000, C_IN=128, C=64, F=2, K+1=4.
// R2: CSR-by-dst spmm (no atomics), 128x64 SIMT GEMM, fused score epilogue.
// ---------------------------------------------------------------------------

#define NMAX 100000
#define EMAX 1600000
#define CDIM 64

__device__ __align__(256) float g_h    [NMAX * CDIM];
__device__ __align__(256) float g_T1   [NMAX * CDIM];
__device__ __align__(256) float g_T2   [NMAX * CDIM];
__device__ __align__(256) float g_T3   [NMAX * CDIM];
__device__ __align__(256) float g_poly [2 * NMAX * CDIM];
__device__ __align__(256) float g_xproj[NMAX * CDIM];
__device__ __align__(256) float g_score[2 * NMAX];
__device__ __align__(256) float g_res  [NMAX * CDIM];
__device__ __align__(256) float g_y1   [NMAX * CDIM];
__device__ __align__(256) float g_y2   [NMAX * 32];
// CSR scratch
__device__ int   g_cnt [NMAX];
__device__ int   g_incl[NMAX];
__device__ int   g_bsum[128];
__device__ int   g_off [NMAX + 1];
__device__ int   g_cur [NMAX];
__device__ int   g_csr_src[EMAX];
__device__ float g_csr_val[EMAX];

__device__ float g_coef[8];   // thetas @ BCOEF, [F=2][K+1=4]
__device__ int   g_is64;

// ---------------------------------------------------------------------------
__global__ void prep_kernel(const void* __restrict__ esrc,
                            const float* __restrict__ thetas)
{
    if (threadIdx.x == 0) {
        const int* w = (const int*)esrc;
        g_is64 = (w[1] == 0 && w[3] == 0 && w[5] == 0 && w[7] == 0) ? 1 : 0;
        const float B[4][4] = {
            {1.f, -3.f,  3.f, -1.f},
            {0.f,  3.f, -6.f,  3.f},
            {0.f,  0.f,  3.f, -3.f},
            {0.f,  0.f,  0.f,  1.f}};
        for (int f = 0; f < 2; f++)
            for (int k = 0; k < 4; k++) {
                float s = 0.f;
                for (int j = 0; j < 4; j++) s += thetas[f * 4 + j] * B[j][k];
                g_coef[f * 4 + k] = s;
            }
    }
}

// ---------------------------------------------------------------------------
// CSR build: count -> scan (3 kernels) -> scatter
// ---------------------------------------------------------------------------
__global__ void count_kernel(const void* __restrict__ edst, int E)
{
    int e = blockIdx.x * blockDim.x + threadIdx.x;
    if (e >= E) return;
    int dst = g_is64 ? (int)((const long long*)edst)[e] : ((const int*)edst)[e];
    atomicAdd(&g_cnt[dst], 1);
}

__global__ void scan1_kernel(int n)
{
    __shared__ int sh[1024];
    int t = threadIdx.x, i = blockIdx.x * 1024 + t;
    int v = (i < n) ? g_cnt[i] : 0;
    sh[t] = v;
    __syncthreads();
    #pragma unroll
    for (int off = 1; off < 1024; off <<= 1) {
        int x = (t >= off) ? sh[t - off] : 0;
        __syncthreads();
        sh[t] += x;
        __syncthreads();
    }
    if (i < n) g_incl[i] = sh[t];
    if (t == 1023) g_bsum[blockIdx.x] = sh[t];
}

__global__ void scan2_kernel(int nb)
{
    __shared__ int sh[128];
    int t = threadIdx.x;
    int v = (t < nb) ? g_bsum[t] : 0;
    sh[t] = v;
    __syncthreads();
    #pragma unroll
    for (int off = 1; off < 128; off <<= 1) {
        int x = (t >= off) ? sh[t - off] : 0;
        __syncthreads();
        sh[t] += x;
        __syncthreads();
    }
    g_bsum[t] = sh[t] - v;          // exclusive block offsets
    if (t == 0) g_off[0] = 0;
}

__global__ void scan3_kernel(int n)
{
    int i = blockIdx.x * blockDim.x + threadIdx.x;
    if (i >= n) return;
    int total = g_incl[i] + g_bsum[i >> 10];
    g_off[i + 1] = total;
    g_cur[i] = total - g_cnt[i];
}

__global__ void scatter_kernel(const void* __restrict__ esrc,
                               const void* __restrict__ edst,
                               const float* __restrict__ ev, int E)
{
    int e = blockIdx.x * blockDim.x + threadIdx.x;
    if (e >= E) return;
    int src, dst;
    if (g_is64) {
        src = (int)((const long long*)esrc)[e];
        dst = (int)((const long long*)edst)[e];
    } else {
        src = ((const int*)esrc)[e];
        dst = ((const int*)edst)[e];
    }
    int pos = atomicAdd(&g_cur[dst], 1);
    g_csr_src[pos] = src;
    g_csr_val[pos] = ev[e];
}

// ---------------------------------------------------------------------------
// CSR spmm: one warp per dst row; lane owns 2 channels (float2).
// out[row,:] = sum_e val_e * hin[src_e,:]   -- gather only, no atomics.
// ---------------------------------------------------------------------------
__global__ void spmm_csr(const float* __restrict__ hin,
                         float* __restrict__ hout, int n)
{
    int w = (blockIdx.x * blockDim.x + threadIdx.x) >> 5;
    int lane = threadIdx.x & 31;
    if (w >= n) return;
    int s = g_off[w], e = g_off[w + 1];
    float2 acc = make_float2(0.f, 0.f);
    for (int i = s; i < e; i++) {
        int   sj = __ldg(&g_csr_src[i]);   // uniform across warp, L1-hit
        float vj = __ldg(&g_csr_val[i]);
        float2 hv = *(const float2*)(hin + (size_t)sj * CDIM + lane * 2);
        acc.x += vj * hv.x;
        acc.y += vj * hv.y;
    }
    *(float2*)(hout + (size_t)w * CDIM + lane * 2) = acc;
}

// ---------------------------------------------------------------------------
// GEMM: C[M,Nout] = act(A[M,K] @ W[K,Nout] + bias). BM=128,BN=64,BK=16,
// 256 threads, 8x4 microtile, float4 everywhere. Nout multiple of 4, <=64.
// ---------------------------------------------------------------------------
__global__ void gemm_v2(const float* __restrict__ A,
                        const float* __restrict__ W,
                        const float* __restrict__ bias,
                        float* __restrict__ C,
                        int M, int K, int Nout, int act)
{
    __shared__ float As[16][132];   // [k][m], 132*4=528B row (16B multiple)
    __shared__ float Bs[16][68];    // [k][n], 272B row

    const int tid = threadIdx.x;
    const int tx = tid & 15;        // n: 4 cols
    const int ty = tid >> 4;        // m: 8 rows
    const int m0 = blockIdx.x * 128;

    float acc[8][4] = {};

    for (int k0 = 0; k0 < K; k0 += 16) {
        // A tile: 128x16 = 512 float4, 2 per thread
        #pragma unroll
        for (int r = 0; r < 2; r++) {
            int i = tid + r * 256;          // float4 index
            int row = i >> 2, kq = i & 3;
            int gm = m0 + row;
            float4 v = make_float4(0.f, 0.f, 0.f, 0.f);
            if (gm < M) v = *(const float4*)(A + (size_t)gm * K + k0 + kq * 4);
            As[kq * 4 + 0][row] = v.x;
            As[kq * 4 + 1][row] = v.y;
            As[kq * 4 + 2][row] = v.z;
            As[kq * 4 + 3][row] = v.w;
        }
        // B tile: 16x64 = 256 float4, 1 per thread
        {
            int k = tid >> 4, n = (tid & 15) * 4;
            float4 v = make_float4(0.f, 0.f, 0.f, 0.f);
            if (n < Nout) v = *(const float4*)(W + (size_t)(k0 + k) * Nout + n);
            Bs[k][n + 0] = v.x; Bs[k][n + 1] = v.y;
            Bs[k][n + 2] = v.z; Bs[k][n + 3] = v.w;
        }
        __syncthreads();
        #pragma unroll
        for (int kk = 0; kk < 16; kk++) {
            float4 a0 = *(const float4*)&As[kk][ty * 8];
            float4 a1 = *(const float4*)&As[kk][ty * 8 + 4];
            float4 b  = *(const float4*)&Bs[kk][tx * 4];
            float am[8] = {a0.x, a0.y, a0.z, a0.w, a1.x, a1.y, a1.z, a1.w};
            float bn[4] = {b.x, b.y, b.z, b.w};
            #pragma unroll
            for (int i = 0; i < 8; i++)
                #pragma unroll
                for (int j = 0; j < 4; j++)
                    acc[i][j] += am[i] * bn[j];
        }
        __syncthreads();
    }

    int n = tx * 4;
    if (n < Nout) {
        float4 bv = *(const float4*)(bias + n);
        #pragma unroll
        for (int i = 0; i < 8; i++) {
            int gm = m0 + ty * 8 + i;
            if (gm >= M) continue;
            float4 o;
            o.x = acc[i][0] + bv.x; o.y = acc[i][1] + bv.y;
            o.z = acc[i][2] + bv.z; o.w = acc[i][3] + bv.w;
            if (act) {
                o.x = fmaxf(o.x, 0.f); o.y = fmaxf(o.y, 0.f);
                o.z = fmaxf(o.z, 0.f); o.w = fmaxf(o.w, 0.f);
            }
            *(float4*)(C + (size_t)gm * Nout + n) = o;
        }
    }
}

// ---------------------------------------------------------------------------
// Fused score GEMM: score[r] = sum_c tanh((poly@Wb)[r,c] + bWb[c]
//                                          + xproj[r>>1,c]) * vc[c]
// A = poly [M=2n x 64], Nout=64 fixed. Same tiling as gemm_v2.
// ---------------------------------------------------------------------------
__global__ void gemm_score(const float* __restrict__ A,
                           const float* __restrict__ W,
                           const float* __restrict__ bias,
                           const float* __restrict__ xproj,
                           const float* __restrict__ vc,
                           float* __restrict__ score, int M)
{
    __shared__ float As[16][132];
    __shared__ float Bs[16][68];

    const int tid = threadIdx.x;
    const int tx = tid & 15;
    const int ty = tid >> 4;
    const int m0 = blockIdx.x * 128;

    float acc[8][4] = {};

    for (int k0 = 0; k0 < 64; k0 += 16) {
        #pragma unroll
        for (int r = 0; r < 2; r++) {
            int i = tid + r * 256;
            int row = i >> 2, kq = i & 3;
            int gm = m0 + row;
            float4 v = make_float4(0.f, 0.f, 0.f, 0.f);
            if (gm < M) v = *(const float4*)(A + (size_t)gm * 64 + k0 + kq * 4);
            As[kq * 4 + 0][row] = v.x;
            As[kq * 4 + 1][row] = v.y;
            As[kq * 4 + 2][row] = v.z;
            As[kq * 4 + 3][row] = v.w;
        }
        {
            int k = tid >> 4, n = (tid & 15) * 4;
            float4 v = *(const float4*)(W + (size_t)(k0 + k) * 64 + n);
            Bs[k][n + 0] = v.x; Bs[k][n + 1] = v.y;
            Bs[k][n + 2] = v.z; Bs[k][n + 3] = v.w;
        }
        __syncthreads();
        #pragma unroll
        for (int kk = 0; kk < 16; kk++) {
            float4 a0 = *(const float4*)&As[kk][ty * 8];
            float4 a1 = *(const float4*)&As[kk][ty * 8 + 4];
            float4 b  = *(const float4*)&Bs[kk][tx * 4];
            float am[8] = {a0.x, a0.y, a0.z, a0.w, a1.x, a1.y, a1.z, a1.w};
            float bn[4] = {b.x, b.y, b.z, b.w};
            #pragma unroll
            for (int i = 0; i < 8; i++)
                #pragma unroll
                for (int j = 0; j < 4; j++)
                    acc[i][j] += am[i] * bn[j];
        }
        __syncthreads();
    }

    int n = tx * 4;
    float4 bv = *(const float4*)(bias + n);
    float4 vv = *(const float4*)(vc + n);
    #pragma unroll
    for (int i = 0; i < 8; i++) {
        int gm = m0 + ty * 8 + i;
        float part = 0.f;
        if (gm < M) {
            const float* xr = xproj + (size_t)(gm >> 1) * 64 + n;
            part += tanhf(acc[i][0] + bv.x + xr[0]) * vv.x;
            part += tanhf(acc[i][1] + bv.y + xr[1]) * vv.y;
            part += tanhf(acc[i][2] + bv.z + xr[2]) * vv.z;
            part += tanhf(acc[i][3] + bv.w + xr[3]) * vv.w;
        }
        // reduce across the 16 tx lanes (lane = tid&31, tx = lane&15)
        #pragma unroll
        for (int o = 8; o > 0; o >>= 1)
            part += __shfl_xor_sync(0xffffffffu, part, o);
        if (tx == 0 && gm < M) score[gm] = part;
    }
}

// ---------------------------------------------------------------------------
// poly[n,f,c] = sum_k coef[f,k] * Tx_k[n,c]
// ---------------------------------------------------------------------------
__global__ void poly_kernel(const float* __restrict__ h,
                            const float* __restrict__ t1,
                            const float* __restrict__ t2,
                            const float* __restrict__ t3,
                            float* __restrict__ poly, int nn)
{
    int idx = blockIdx.x * blockDim.x + threadIdx.x;
    if (idx >= nn * 16) return;
    int n = idx >> 4, q = idx & 15;

    float4 a = ((const float4*)h)[idx];
    float4 b = ((const float4*)t1)[idx];
    float4 c = ((const float4*)t2)[idx];
    float4 d = ((const float4*)t3)[idx];

    float c00 = g_coef[0], c01 = g_coef[1], c02 = g_coef[2], c03 = g_coef[3];
    float c10 = g_coef[4], c11 = g_coef[5], c12 = g_coef[6], c13 = g_coef[7];

    float4 p0, p1;
    p0.x = c00*a.x + c01*b.x + c02*c.x + c03*d.x;
    p0.y = c00*a.y + c01*b.y + c02*c.y + c03*d.y;
    p0.z = c00*a.z + c01*b.z + c02*c.z + c03*d.z;
    p0.w = c00*a.w + c01*b.w + c02*c.w + c03*d.w;
    p1.x = c10*a.x + c11*b.x + c12*c.x + c13*d.x;
    p1.y = c10*a.y + c11*b.y + c12*c.y + c13*d.y;
    p1.z = c10*a.z + c11*b.z + c12*c.z + c13*d.z;
    p1.w = c10*a.w + c11*b.w + c12*c.w + c13*d.w;

    ((float4*)poly)[(size_t)n * 32 + q]      = p0;
    ((float4*)poly)[(size_t)n * 32 + 16 + q] = p1;
}

// ---------------------------------------------------------------------------
// Attention combine: softmax over F=2 scores, res = a0*poly0 + a1*poly1
// ---------------------------------------------------------------------------
__global__ void attn_kernel(const float* __restrict__ poly,
                            const float* __restrict__ score,
                            float* __restrict__ res, int nn)
{
    int idx = blockIdx.x * blockDim.x + threadIdx.x;   // nn*16 float4s
    if (idx >= nn * 16) return;
    int n = idx >> 4, q = idx & 15;

    float s0 = score[2 * n], s1 = score[2 * n + 1];
    float m = fmaxf(s0, s1);
    float e0 = expf(s0 - m), e1 = expf(s1 - m);
    float inv = 1.f / (e0 + e1);
    float a0 = e0 * inv, a1 = e1 * inv;

    float4 p0 = ((const float4*)poly)[(size_t)n * 32 + q];
    float4 p1 = ((const float4*)poly)[(size_t)n * 32 + 16 + q];
    float4 o;
    o.x = a0 * p0.x + a1 * p1.x;
    o.y = a0 * p0.y + a1 * p1.y;
    o.z = a0 * p0.z + a1 * p1.z;
    o.w = a0 * p0.w + a1 * p1.w;
    ((float4*)res)[idx] = o;
}

// ---------------------------------------------------------------------------
__global__ void head_kernel(const float* __restrict__ y2,
                            const float* __restrict__ W3,
                            const float* __restrict__ b3,
                            float* __restrict__ out, int nn)
{
    int n = blockIdx.x * blockDim.x + threadIdx.x;
    if (n >= nn) return;
    float s0 = b3[0], s1 = b3[1];
    const float* row = y2 + (size_t)n * 32;
    #pragma unroll
    for (int c = 0; c < 32; c++) {
        float v = row[c];
        s0 += v * W3[c * 2];
        s1 += v * W3[c * 2 + 1];
    }
    out[n * 2]     = s0;
    out[n * 2 + 1] = s1;
}

// ---------------------------------------------------------------------------
extern "C" void kernel_launch(void* const* d_in, const int* in_sizes, int n_in,
                              void* d_out, int out_size)
{
    const float* x      = (const float*)d_in[0];
    const void*  esrc   = d_in[1];
    const void*  edst   = d_in[2];
    const float* ev     = (const float*)d_in[3];
    const float* Win    = (const float*)d_in[4];
    const float* bin    = (const float*)d_in[5];
    const float* thetas = (const float*)d_in[6];
    const float* Wb     = (const float*)d_in[7];
    const float* bWb    = (const float*)d_in[8];
    const float* Wx     = (const float*)d_in[9];
    const float* bWx    = (const float*)d_in[10];
    const float* vc     = (const float*)d_in[11];
    const float* W1     = (const float*)d_in[12];
    const float* b1     = (const float*)d_in[13];
    const float* W2     = (const float*)d_in[14];
    const float* b2     = (const float*)d_in[15];
    const float* W3     = (const float*)d_in[16];
    const float* b3     = (const float*)d_in[17];

    int n = in_sizes[0] / 128;
    int E = in_sizes[3];

    float *ph, *pT1, *pT2, *pT3, *ppoly, *pxp, *pscore, *pres, *py1, *py2;
    int* pcnt;
    cudaGetSymbolAddress((void**)&ph,     g_h);
    cudaGetSymbolAddress((void**)&pT1,    g_T1);
    cudaGetSymbolAddress((void**)&pT2,    g_T2);
    cudaGetSymbolAddress((void**)&pT3,    g_T3);
    cudaGetSymbolAddress((void**)&ppoly,  g_poly);
    cudaGetSymbolAddress((void**)&pxp,    g_xproj);
    cudaGetSymbolAddress((void**)&pscore, g_score);
    cudaGetSymbolAddress((void**)&pres,   g_res);
    cudaGetSymbolAddress((void**)&py1,    g_y1);
    cudaGetSymbolAddress((void**)&py2,    g_y2);
    cudaGetSymbolAddress((void**)&pcnt,   g_cnt);

    prep_kernel<<<1, 32>>>(esrc, thetas);

    // ---- CSR build ----
    cudaMemsetAsync(pcnt, 0, n * sizeof(int), 0);
    count_kernel<<<(E + 255) / 256, 256>>>(edst, E);
    int nb = (n + 1023) / 1024;
    scan1_kernel<<<nb, 1024>>>(n);
    scan2_kernel<<<1, 128>>>(nb);
    scan3_kernel<<<(n + 255) / 256, 256>>>(n);
    scatter_kernel<<<(E + 255) / 256, 256>>>(esrc, edst, ev, E);

    // ---- h = relu(x @ W_in + b_in) ----
    gemm_v2<<<(n + 127) / 128, 256>>>(x, Win, bin, ph, n, 128, 64, 1);

    // ---- 3-hop propagation (gather-only spmm) ----
    int sb = (n * 32 + 255) / 256;
    spmm_csr<<<sb, 256>>>(ph,  pT1, n);
    spmm_csr<<<sb, 256>>>(pT1, pT2, n);
    spmm_csr<<<sb, 256>>>(pT2, pT3, n);

    // ---- poly ----
    poly_kernel<<<(n * 16 + 255) / 256, 256>>>(ph, pT1, pT2, pT3, ppoly, n);

    // ---- attention ----
    gemm_v2<<<(n + 127) / 128, 256>>>(ph, Wx, bWx, pxp, n, 64, 64, 0);
    gemm_score<<<(2 * n + 127) / 128, 256>>>(ppoly, Wb, bWb, pxp, vc, pscore, 2 * n);
    attn_kernel<<<(n * 16 + 255) / 256, 256>>>(ppoly, pscore, pres, n);

    // ---- classifier head ----
    gemm_v2<<<(n + 127) / 128, 256>>>(pres, W1, b1, py1, n, 64, 64, 1);
    gemm_v2<<<(n + 127) / 128, 256>>>(py1, W2, b2, py2, n, 64, 32, 1);
    head_kernel<<<(n + 255) / 256, 256>>>(py2, W3, b3, (float*)d_out, n);
}

// round 3
// speedup vs baseline: 1.8184x; 1.1397x over previous
#include <cuda_runtime.h>
#include <cstdint>

// ---------------------------------------------------------------------------
// NodeBernNet fixed shapes: N=100000, E=1600000, C_IN=128, C=64, F=2, K+1=4.
// R3: spmm3+poly fusion; fused attn+MLP tail; float4 2-row/warp spmm.
// ---------------------------------------------------------------------------

#define NMAX 100000
#define EMAX 1600000
#define CDIM 64

__device__ __align__(256) float g_h    [NMAX * CDIM];
__device__ __align__(256) float g_T1   [NMAX * CDIM];
__device__ __align__(256) float g_T2   [NMAX * CDIM];
__device__ __align__(256) float g_poly [2 * NMAX * CDIM];
__device__ __align__(256) float g_xproj[NMAX * CDIM];
__device__ __align__(256) float g_score[2 * NMAX];
// CSR scratch
__device__ int   g_cnt [NMAX];
__device__ int   g_incl[NMAX];
__device__ int   g_bsum[128];
__device__ int   g_off [NMAX + 1];
__device__ int   g_cur [NMAX];
__device__ int   g_csr_src[EMAX];
__device__ float g_csr_val[EMAX];

__device__ float g_coef[8];   // thetas @ BCOEF, [F=2][K+1=4]
__device__ int   g_is64;

// ---------------------------------------------------------------------------
__global__ void prep_kernel(const void* __restrict__ esrc,
                            const float* __restrict__ thetas)
{
    if (threadIdx.x == 0) {
        const int* w = (const int*)esrc;
        g_is64 = (w[1] == 0 && w[3] == 0 && w[5] == 0 && w[7] == 0) ? 1 : 0;
        const float B[4][4] = {
            {1.f, -3.f,  3.f, -1.f},
            {0.f,  3.f, -6.f,  3.f},
            {0.f,  0.f,  3.f, -3.f},
            {0.f,  0.f,  0.f,  1.f}};
        for (int f = 0; f < 2; f++)
            for (int k = 0; k < 4; k++) {
                float s = 0.f;
                for (int j = 0; j < 4; j++) s += thetas[f * 4 + j] * B[j][k];
                g_coef[f * 4 + k] = s;
            }
    }
}

// ---------------------------------------------------------------------------
// CSR build
// ---------------------------------------------------------------------------
__global__ void count_kernel(const void* __restrict__ edst, int E)
{
    int e = blockIdx.x * blockDim.x + threadIdx.x;
    if (e >= E) return;
    int dst = g_is64 ? (int)((const long long*)edst)[e] : ((const int*)edst)[e];
    atomicAdd(&g_cnt[dst], 1);
}

__global__ void scan1_kernel(int n)
{
    __shared__ int sh[1024];
    int t = threadIdx.x, i = blockIdx.x * 1024 + t;
    int v = (i < n) ? g_cnt[i] : 0;
    sh[t] = v;
    __syncthreads();
    #pragma unroll
    for (int off = 1; off < 1024; off <<= 1) {
        int x = (t >= off) ? sh[t - off] : 0;
        __syncthreads();
        sh[t] += x;
        __syncthreads();
    }
    if (i < n) g_incl[i] = sh[t];
    if (t == 1023) g_bsum[blockIdx.x] = sh[t];
}

__global__ void scan2_kernel(int nb)
{
    __shared__ int sh[128];
    int t = threadIdx.x;
    int v = (t < nb) ? g_bsum[t] : 0;
    sh[t] = v;
    __syncthreads();
    #pragma unroll
    for (int off = 1; off < 128; off <<= 1) {
        int x = (t >= off) ? sh[t - off] : 0;
        __syncthreads();
        sh[t] += x;
        __syncthreads();
    }
    g_bsum[t] = sh[t] - v;
    if (t == 0) g_off[0] = 0;
}

__global__ void scan3_kernel(int n)
{
    int i = blockIdx.x * blockDim.x + threadIdx.x;
    if (i >= n) return;
    int total = g_incl[i] + g_bsum[i >> 10];
    g_off[i + 1] = total;
    g_cur[i] = total - g_cnt[i];
}

__global__ void scatter_kernel(const void* __restrict__ esrc,
                               const void* __restrict__ edst,
                               const float* __restrict__ ev, int E)
{
    int e = blockIdx.x * blockDim.x + threadIdx.x;
    if (e >= E) return;
    int src, dst;
    if (g_is64) {
        src = (int)((const long long*)esrc)[e];
        dst = (int)((const long long*)edst)[e];
    } else {
        src = ((const int*)esrc)[e];
        dst = ((const int*)edst)[e];
    }
    int pos = atomicAdd(&g_cur[dst], 1);
    g_csr_src[pos] = src;
    g_csr_val[pos] = ev[e];
}

// ---------------------------------------------------------------------------
// CSR spmm: 2 rows per warp, float4 per 16-lane half, unroll-2 inner loop.
// ---------------------------------------------------------------------------
__device__ __forceinline__ float4 spmm_row_acc(const float* __restrict__ hin,
                                               int s, int e, int lane16)
{
    float4 acc = make_float4(0.f, 0.f, 0.f, 0.f);
    int i = s;
    for (; i + 1 < e; i += 2) {
        int   s0 = __ldg(&g_csr_src[i]);
        int   s1 = __ldg(&g_csr_src[i + 1]);
        float v0 = __ldg(&g_csr_val[i]);
        float v1 = __ldg(&g_csr_val[i + 1]);
        float4 h0 = *((const float4*)(hin + (size_t)s0 * CDIM) + lane16);
        float4 h1 = *((const float4*)(hin + (size_t)s1 * CDIM) + lane16);
        acc.x += v0 * h0.x + v1 * h1.x;
        acc.y += v0 * h0.y + v1 * h1.y;
        acc.z += v0 * h0.z + v1 * h1.z;
        acc.w += v0 * h0.w + v1 * h1.w;
    }
    if (i < e) {
        int   s0 = __ldg(&g_csr_src[i]);
        float v0 = __ldg(&g_csr_val[i]);
        float4 h0 = *((const float4*)(hin + (size_t)s0 * CDIM) + lane16);
        acc.x += v0 * h0.x; acc.y += v0 * h0.y;
        acc.z += v0 * h0.z; acc.w += v0 * h0.w;
    }
    return acc;
}

__global__ void spmm_csr(const float* __restrict__ hin,
                         float* __restrict__ hout, int n)
{
    int w = (blockIdx.x * blockDim.x + threadIdx.x) >> 5;
    int lane = threadIdx.x & 31;
    int r = w * 2 + (lane >> 4);
    if (r >= n) return;
    int lane16 = lane & 15;
    float4 acc = spmm_row_acc(hin, g_off[r], g_off[r + 1], lane16);
    *((float4*)(hout + (size_t)r * CDIM) + lane16) = acc;
}

// spmm #3 fused with poly: T3 row stays in registers; poly written directly.
__global__ void spmm_poly(const float* __restrict__ h,
                          const float* __restrict__ t1,
                          const float* __restrict__ t2,
                          float* __restrict__ poly, int n)
{
    int w = (blockIdx.x * blockDim.x + threadIdx.x) >> 5;
    int lane = threadIdx.x & 31;
    int r = w * 2 + (lane >> 4);
    if (r >= n) return;
    int lane16 = lane & 15;
    float4 d = spmm_row_acc(t2, g_off[r], g_off[r + 1], lane16);   // T3 row

    float4 a = *((const float4*)(h  + (size_t)r * CDIM) + lane16);
    float4 b = *((const float4*)(t1 + (size_t)r * CDIM) + lane16);
    float4 c = *((const float4*)(t2 + (size_t)r * CDIM) + lane16);

    float c00 = g_coef[0], c01 = g_coef[1], c02 = g_coef[2], c03 = g_coef[3];
    float c10 = g_coef[4], c11 = g_coef[5], c12 = g_coef[6], c13 = g_coef[7];

    float4 p0, p1;
    p0.x = c00*a.x + c01*b.x + c02*c.x + c03*d.x;
    p0.y = c00*a.y + c01*b.y + c02*c.y + c03*d.y;
    p0.z = c00*a.z + c01*b.z + c02*c.z + c03*d.z;
    p0.w = c00*a.w + c01*b.w + c02*c.w + c03*d.w;
    p1.x = c10*a.x + c11*b.x + c12*c.x + c13*d.x;
    p1.y = c10*a.y + c11*b.y + c12*c.y + c13*d.y;
    p1.z = c10*a.z + c11*b.z + c12*c.z + c13*d.z;
    p1.w = c10*a.w + c11*b.w + c12*c.w + c13*d.w;

    ((float4*)poly)[((size_t)r * 2    ) * 16 + lane16] = p0;
    ((float4*)poly)[((size_t)r * 2 + 1) * 16 + lane16] = p1;
}

// ---------------------------------------------------------------------------
// GEMM: C = act(A@W + bias). BM=128, BN<=64, BK=16, 256 thr, 8x4 microtile.
// ---------------------------------------------------------------------------
__global__ void gemm_v2(const float* __restrict__ A,
                        const float* __restrict__ W,
                        const float* __restrict__ bias,
                        float* __restrict__ C,
                        int M, int K, int Nout, int act)
{
    __shared__ float As[16][132];
    __shared__ float Bs[16][68];

    const int tid = threadIdx.x;
    const int tx = tid & 15;
    const int ty = tid >> 4;
    const int m0 = blockIdx.x * 128;

    float acc[8][4] = {};

    for (int k0 = 0; k0 < K; k0 += 16) {
        #pragma unroll
        for (int r = 0; r < 2; r++) {
            int i = tid + r * 256;
            int row = i >> 2, kq = i & 3;
            int gm = m0 + row;
            float4 v = make_float4(0.f, 0.f, 0.f, 0.f);
            if (gm < M) v = *(const float4*)(A + (size_t)gm * K + k0 + kq * 4);
            As[kq * 4 + 0][row] = v.x;
            As[kq * 4 + 1][row] = v.y;
            As[kq * 4 + 2][row] = v.z;
            As[kq * 4 + 3][row] = v.w;
        }
        {
            int k = tid >> 4, nn = (tid & 15) * 4;
            float4 v = make_float4(0.f, 0.f, 0.f, 0.f);
            if (nn < Nout) v = *(const float4*)(W + (size_t)(k0 + k) * Nout + nn);
            Bs[k][nn + 0] = v.x; Bs[k][nn + 1] = v.y;
            Bs[k][nn + 2] = v.z; Bs[k][nn + 3] = v.w;
        }
        __syncthreads();
        #pragma unroll
        for (int kk = 0; kk < 16; kk++) {
            float4 a0 = *(const float4*)&As[kk][ty * 8];
            float4 a1 = *(const float4*)&As[kk][ty * 8 + 4];
            float4 b  = *(const float4*)&Bs[kk][tx * 4];
            float am[8] = {a0.x, a0.y, a0.z, a0.w, a1.x, a1.y, a1.z, a1.w};
            float bn[4] = {b.x, b.y, b.z, b.w};
            #pragma unroll
            for (int i = 0; i < 8; i++)
                #pragma unroll
                for (int j = 0; j < 4; j++)
                    acc[i][j] += am[i] * bn[j];
        }
        __syncthreads();
    }

    int nn = tx * 4;
    if (nn < Nout) {
        float4 bv = *(const float4*)(bias + nn);
        #pragma unroll
        for (int i = 0; i < 8; i++) {
            int gm = m0 + ty * 8 + i;
            if (gm >= M) continue;
            float4 o;
            o.x = acc[i][0] + bv.x; o.y = acc[i][1] + bv.y;
            o.z = acc[i][2] + bv.z; o.w = acc[i][3] + bv.w;
            if (act) {
                o.x = fmaxf(o.x, 0.f); o.y = fmaxf(o.y, 0.f);
                o.z = fmaxf(o.z, 0.f); o.w = fmaxf(o.w, 0.f);
            }
            *(float4*)(C + (size_t)gm * Nout + nn) = o;
        }
    }
}

// ---------------------------------------------------------------------------
// Fused score GEMM: score[r] = sum_c tanh((poly@Wb)[r,c]+bWb[c]+xproj[r>>1,c])*vc[c]
// ---------------------------------------------------------------------------
__global__ void gemm_score(const float* __restrict__ A,
                           const float* __restrict__ W,
                           const float* __restrict__ bias,
                           const float* __restrict__ xproj,
                           const float* __restrict__ vc,
                           float* __restrict__ score, int M)
{
    __shared__ float As[16][132];
    __shared__ float Bs[16][68];

    const int tid = threadIdx.x;
    const int tx = tid & 15;
    const int ty = tid >> 4;
    const int m0 = blockIdx.x * 128;

    float acc[8][4] = {};

    for (int k0 = 0; k0 < 64; k0 += 16) {
        #pragma unroll
        for (int r = 0; r < 2; r++) {
            int i = tid + r * 256;
            int row = i >> 2, kq = i & 3;
            int gm = m0 + row;
            float4 v = make_float4(0.f, 0.f, 0.f, 0.f);
            if (gm < M) v = *(const float4*)(A + (size_t)gm * 64 + k0 + kq * 4);
            As[kq * 4 + 0][row] = v.x;
            As[kq * 4 + 1][row] = v.y;
            As[kq * 4 + 2][row] = v.z;
            As[kq * 4 + 3][row] = v.w;
        }
        {
            int k = tid >> 4, nn = (tid & 15) * 4;
            float4 v = *(const float4*)(W + (size_t)(k0 + k) * 64 + nn);
            Bs[k][nn + 0] = v.x; Bs[k][nn + 1] = v.y;
            Bs[k][nn + 2] = v.z; Bs[k][nn + 3] = v.w;
        }
        __syncthreads();
        #pragma unroll
        for (int kk = 0; kk < 16; kk++) {
            float4 a0 = *(const float4*)&As[kk][ty * 8];
            float4 a1 = *(const float4*)&As[kk][ty * 8 + 4];
            float4 b  = *(const float4*)&Bs[kk][tx * 4];
            float am[8] = {a0.x, a0.y, a0.z, a0.w, a1.x, a1.y, a1.z, a1.w};
            float bn[4] = {b.x, b.y, b.z, b.w};
            #pragma unroll
            for (int i = 0; i < 8; i++)
                #pragma unroll
                for (int j = 0; j < 4; j++)
                    acc[i][j] += am[i] * bn[j];
        }
        __syncthreads();
    }

    int nn = tx * 4;
    float4 bv = *(const float4*)(bias + nn);
    float4 vv = *(const float4*)(vc + nn);
    #pragma unroll
    for (int i = 0; i < 8; i++) {
        int gm = m0 + ty * 8 + i;
        float part = 0.f;
        if (gm < M) {
            const float* xr = xproj + (size_t)(gm >> 1) * 64 + nn;
            part += tanhf(acc[i][0] + bv.x + xr[0]) * vv.x;
            part += tanhf(acc[i][1] + bv.y + xr[1]) * vv.y;
            part += tanhf(acc[i][2] + bv.z + xr[2]) * vv.z;
            part += tanhf(acc[i][3] + bv.w + xr[3]) * vv.w;
        }
        #pragma unroll
        for (int o = 8; o > 0; o >>= 1)
            part += __shfl_xor_sync(0xffffffffu, part, o);
        if (tx == 0 && gm < M) score[gm] = part;
    }
}

// ---------------------------------------------------------------------------
// Fused tail: attn combine -> y1=relu(res@W1+b1) -> y2=relu(y1@W2+b2)
//             -> out = y2@W3+b3.   64 nodes per block, 256 threads.
// ---------------------------------------------------------------------------
__global__ void tail_kernel(const float* __restrict__ poly,
                            const float* __restrict__ score,
                            const float* __restrict__ W1,
                            const float* __restrict__ b1,
                            const float* __restrict__ W2,
                            const float* __restrict__ b2,
                            const float* __restrict__ W3,
                            const float* __restrict__ b3,
                            float* __restrict__ out, int nn)
{
    __shared__ float As[64][68];   // [k][m] A-operand for current stage
    __shared__ float Bs[64][68];   // [k][n] weights

    const int tid = threadIdx.x;
    const int b0 = blockIdx.x * 64;

    // ---- Stage 0: res (attn combine), write transposed into As ----
    #pragma unroll
    for (int r = 0; r < 4; r++) {
        int it = tid + r * 256;          // 0..1023 over 64 nodes x 16 float4
        int nl = it >> 4, q = it & 15;
        int gn = b0 + nl;
        float4 v = make_float4(0.f, 0.f, 0.f, 0.f);
        if (gn < nn) {
            float s0 = score[2 * gn], s1 = score[2 * gn + 1];
            float m = fmaxf(s0, s1);
            float e0 = expf(s0 - m), e1 = expf(s1 - m);
            float inv = 1.f / (e0 + e1);
            float a0 = e0 * inv, a1 = e1 * inv;
            float4 p0 = ((const float4*)poly)[((size_t)gn * 2    ) * 16 + q];
            float4 p1 = ((const float4*)poly)[((size_t)gn * 2 + 1) * 16 + q];
            v.x = a0 * p0.x + a1 * p1.x;
            v.y = a0 * p0.y + a1 * p1.y;
            v.z = a0 * p0.z + a1 * p1.z;
            v.w = a0 * p0.w + a1 * p1.w;
        }
        As[q * 4 + 0][nl] = v.x;
        As[q * 4 + 1][nl] = v.y;
        As[q * 4 + 2][nl] = v.z;
        As[q * 4 + 3][nl] = v.w;
    }
    // load W1 into Bs
    #pragma unroll
    for (int r = 0; r < 4; r++) {
        int i = tid + r * 256;           // 1024 float4s = 64x64 floats
        int k = i >> 4, nq = (i & 15) * 4;
        float4 v = *(const float4*)(W1 + (size_t)k * 64 + nq);
        Bs[k][nq + 0] = v.x; Bs[k][nq + 1] = v.y;
        Bs[k][nq + 2] = v.z; Bs[k][nq + 3] = v.w;
    }
    __syncthreads();

    // ---- Stage 1: y1 = relu(res @ W1 + b1), 4x4 microtile ----
    const int tx = tid & 15;   // 16 x 4 cols = 64
    const int ty = tid >> 4;   // 16 x 4 rows = 64
    float acc[4][4] = {};
    #pragma unroll
    for (int kk = 0; kk < 64; kk++) {
        float4 a = *(const float4*)&As[kk][ty * 4];
        float4 b = *(const float4*)&Bs[kk][tx * 4];
        float am[4] = {a.x, a.y, a.z, a.w};
        float bn[4] = {b.x, b.y, b.z, b.w};
        #pragma unroll
        for (int i = 0; i < 4; i++)
            #pragma unroll
            for (int j = 0; j < 4; j++)
                acc[i][j] += am[i] * bn[j];
    }
    __syncthreads();   // everyone done reading As/Bs

    // write y1 transposed into As; load W2 into Bs
    {
        float4 bv = *(const float4*)(b1 + tx * 4);
        float bb[4] = {bv.x, bv.y, bv.z, bv.w};
        #pragma unroll
        for (int i = 0; i < 4; i++)
            #pragma unroll
            for (int j = 0; j < 4; j++)
                As[tx * 4 + j][ty * 4 + i] = fmaxf(acc[i][j] + bb[j], 0.f);
    }
    #pragma unroll
    for (int r = 0; r < 2; r++) {
        int i = tid + r * 256;           // 512 float4s = 64x32 floats
        int k = i >> 3, nq = (i & 7) * 4;
        float4 v = *(const float4*)(W2 + (size_t)k * 32 + nq);
        Bs[k][nq + 0] = v.x; Bs[k][nq + 1] = v.y;
        Bs[k][nq + 2] = v.z; Bs[k][nq + 3] = v.w;
    }
    __syncthreads();

    // ---- Stage 2: y2 = relu(y1 @ W2 + b2); 4 rows x 2 cols per thread ----
    const int tx2 = tid & 15;   // 16 x 2 cols = 32
    const int ty2 = tid >> 4;   // 16 x 4 rows = 64
    float acc2[4][2] = {};
    #pragma unroll
    for (int kk = 0; kk < 64; kk++) {
        float4 a = *(const float4*)&As[kk][ty2 * 4];
        float b0v = Bs[kk][tx2 * 2];
        float b1v = Bs[kk][tx2 * 2 + 1];
        float am[4] = {a.x, a.y, a.z, a.w};
        #pragma unroll
        for (int i = 0; i < 4; i++) {
            acc2[i][0] += am[i] * b0v;
            acc2[i][1] += am[i] * b1v;
        }
    }
    float bb0 = b2[tx2 * 2], bb1 = b2[tx2 * 2 + 1];
    float w00 = W3[(tx2 * 2) * 2],     w01 = W3[(tx2 * 2) * 2 + 1];
    float w10 = W3[(tx2 * 2 + 1) * 2], w11 = W3[(tx2 * 2 + 1) * 2 + 1];

    // ---- Stage 3: out = y2 @ W3 + b3, reduce across 16 tx2 lanes ----
    #pragma unroll
    for (int i = 0; i < 4; i++) {
        float y0 = fmaxf(acc2[i][0] + bb0, 0.f);
        float y1v = fmaxf(acc2[i][1] + bb1, 0.f);
        float s0 = y0 * w00 + y1v * w10;
        float s1 = y0 * w01 + y1v * w11;
        #pragma unroll
        for (int o = 8; o > 0; o >>= 1) {
            s0 += __shfl_xor_sync(0xffffffffu, s0, o);
            s1 += __shfl_xor_sync(0xffffffffu, s1, o);
        }
        int gm = b0 + ty2 * 4 + i;
        if (tx2 == 0 && gm < nn) {
            out[gm * 2]     = s0 + b3[0];
            out[gm * 2 + 1] = s1 + b3[1];
        }
    }
}

// ---------------------------------------------------------------------------
extern "C" void kernel_launch(void* const* d_in, const int* in_sizes, int n_in,
                              void* d_out, int out_size)
{
    const float* x      = (const float*)d_in[0];
    const void*  esrc   = d_in[1];
    const void*  edst   = d_in[2];
    const float* ev     = (const float*)d_in[3];
    const float* Win    = (const float*)d_in[4];
    const float* bin    = (const float*)d_in[5];
    const float* thetas = (const float*)d_in[6];
    const float* Wb     = (const float*)d_in[7];
    const float* bWb    = (const float*)d_in[8];
    const float* Wx     = (const float*)d_in[9];
    const float* bWx    = (const float*)d_in[10];
    const float* vc     = (const float*)d_in[11];
    const float* W1     = (const float*)d_in[12];
    const float* b1     = (const float*)d_in[13];
    const float* W2     = (const float*)d_in[14];
    const float* b2     = (const float*)d_in[15];
    const float* W3     = (const float*)d_in[16];
    const float* b3     = (const float*)d_in[17];

    int n = in_sizes[0] / 128;
    int E = in_sizes[3];

    float *ph, *pT1, *pT2, *ppoly, *pxp, *pscore;
    int* pcnt;
    cudaGetSymbolAddress((void**)&ph,     g_h);
    cudaGetSymbolAddress((void**)&pT1,    g_T1);
    cudaGetSymbolAddress((void**)&pT2,    g_T2);
    cudaGetSymbolAddress((void**)&ppoly,  g_poly);
    cudaGetSymbolAddress((void**)&pxp,    g_xproj);
    cudaGetSymbolAddress((void**)&pscore, g_score);
    cudaGetSymbolAddress((void**)&pcnt,   g_cnt);

    prep_kernel<<<1, 32>>>(esrc, thetas);

    // ---- CSR build ----
    cudaMemsetAsync(pcnt, 0, n * sizeof(int), 0);
    count_kernel<<<(E + 255) / 256, 256>>>(edst, E);
    int nb = (n + 1023) / 1024;
    scan1_kernel<<<nb, 1024>>>(n);
    scan2_kernel<<<1, 128>>>(nb);
    scan3_kernel<<<(n + 255) / 256, 256>>>(n);
    scatter_kernel<<<(E + 255) / 256, 256>>>(esrc, edst, ev, E);

    // ---- h = relu(x @ W_in + b_in) ----
    gemm_v2<<<(n + 127) / 128, 256>>>(x, Win, bin, ph, n, 128, 64, 1);

    // ---- propagation ----
    int warps = (n + 1) / 2;
    int sb = (warps * 32 + 255) / 256;
    spmm_csr<<<sb, 256>>>(ph,  pT1, n);
    spmm_csr<<<sb, 256>>>(pT1, pT2, n);
    spmm_poly<<<sb, 256>>>(ph, pT1, pT2, ppoly, n);

    // ---- attention scores ----
    gemm_v2<<<(n + 127) / 128, 256>>>(ph, Wx, bWx, pxp, n, 64, 64, 0);
    gemm_score<<<(2 * n + 127) / 128, 256>>>(ppoly, Wb, bWb, pxp, vc, pscore, 2 * n);

    // ---- fused attn + MLP head ----
    tail_kernel<<<(n + 63) / 64, 256>>>(ppoly, pscore, W1, b1, W2, b2, W3, b3,
                                        (float*)d_out, n);
}

// round 4
// speedup vs baseline: 1.8750x; 1.0312x over previous
#include <cuda_runtime.h>
#include <cstdint>

// ---------------------------------------------------------------------------
// NodeBernNet fixed shapes: N=100000, E=1600000, C_IN=128, C=64, F=2, K+1=4.
// R4: mega-tail fusion (xproj+score+attn+MLP in one kernel), GEMM||count
// overlap, interleaved int2 CSR + unroll-4 spmm.
// ---------------------------------------------------------------------------

#define NMAX 100000
#define EMAX 1600000
#define CDIM 64

__device__ __align__(256) float g_h    [NMAX * CDIM];
__device__ __align__(256) float g_T1   [NMAX * CDIM];
__device__ __align__(256) float g_T2   [NMAX * CDIM];
__device__ __align__(256) float g_poly [2 * NMAX * CDIM];
// CSR scratch
__device__ int   g_cnt [NMAX];
__device__ int   g_incl[NMAX];
__device__ int   g_bsum[128];
__device__ int   g_off [NMAX + 1];
__device__ int   g_cur [NMAX];
__device__ __align__(16) int2 g_csr[EMAX];   // {src, val bits}

__device__ float g_coef[8];   // thetas @ BCOEF, [F=2][K+1=4]
__device__ int   g_is64;

// ---------------------------------------------------------------------------
__global__ void prep_kernel(const void* __restrict__ esrc,
                            const float* __restrict__ thetas)
{
    if (threadIdx.x == 0) {
        const int* w = (const int*)esrc;
        g_is64 = (w[1] == 0 && w[3] == 0 && w[5] == 0 && w[7] == 0) ? 1 : 0;
        const float B[4][4] = {
            {1.f, -3.f,  3.f, -1.f},
            {0.f,  3.f, -6.f,  3.f},
            {0.f,  0.f,  3.f, -3.f},
            {0.f,  0.f,  0.f,  1.f}};
        for (int f = 0; f < 2; f++)
            for (int k = 0; k < 4; k++) {
                float s = 0.f;
                for (int j = 0; j < 4; j++) s += thetas[f * 4 + j] * B[j][k];
                g_coef[f * 4 + k] = s;
            }
    }
}

// ---------------------------------------------------------------------------
// Fat kernel: blocks [0,GB) do h = relu(x @ W_in + b_in) (K=128, Nout=64);
// blocks [GB, GB+CB) do the edge-dst histogram. Independent work overlapped.
// ---------------------------------------------------------------------------
__global__ void gemm_count(const float* __restrict__ A,
                           const float* __restrict__ W,
                           const float* __restrict__ bias,
                           float* __restrict__ C, int M,
                           const void* __restrict__ edst, int E, int GB)
{
    if ((int)blockIdx.x >= GB) {
        int e = (blockIdx.x - GB) * blockDim.x + threadIdx.x;
        if (e < E) {
            int dst = g_is64 ? (int)((const long long*)edst)[e]
                             : ((const int*)edst)[e];
            atomicAdd(&g_cnt[dst], 1);
        }
        return;
    }

    __shared__ float As[16][132];
    __shared__ float Bs[16][68];

    const int tid = threadIdx.x;
    const int tx = tid & 15;
    const int ty = tid >> 4;
    const int m0 = blockIdx.x * 128;

    float acc[8][4] = {};

    for (int k0 = 0; k0 < 128; k0 += 16) {
        #pragma unroll
        for (int r = 0; r < 2; r++) {
            int i = tid + r * 256;
            int row = i >> 2, kq = i & 3;
            int gm = m0 + row;
            float4 v = make_float4(0.f, 0.f, 0.f, 0.f);
            if (gm < M) v = *(const float4*)(A + (size_t)gm * 128 + k0 + kq * 4);
            As[kq * 4 + 0][row] = v.x;
            As[kq * 4 + 1][row] = v.y;
            As[kq * 4 + 2][row] = v.z;
            As[kq * 4 + 3][row] = v.w;
        }
        {
            int k = tid >> 4, nn = (tid & 15) * 4;
            float4 v = *(const float4*)(W + (size_t)(k0 + k) * 64 + nn);
            Bs[k][nn + 0] = v.x; Bs[k][nn + 1] = v.y;
            Bs[k][nn + 2] = v.z; Bs[k][nn + 3] = v.w;
        }
        __syncthreads();
        #pragma unroll
        for (int kk = 0; kk < 16; kk++) {
            float4 a0 = *(const float4*)&As[kk][ty * 8];
            float4 a1 = *(const float4*)&As[kk][ty * 8 + 4];
            float4 b  = *(const float4*)&Bs[kk][tx * 4];
            float am[8] = {a0.x, a0.y, a0.z, a0.w, a1.x, a1.y, a1.z, a1.w};
            float bn[4] = {b.x, b.y, b.z, b.w};
            #pragma unroll
            for (int i = 0; i < 8; i++)
                #pragma unroll
                for (int j = 0; j < 4; j++)
                    acc[i][j] += am[i] * bn[j];
        }
        __syncthreads();
    }

    int nn = tx * 4;
    float4 bv = *(const float4*)(bias + nn);
    #pragma unroll
    for (int i = 0; i < 8; i++) {
        int gm = m0 + ty * 8 + i;
        if (gm >= M) continue;
        float4 o;
        o.x = fmaxf(acc[i][0] + bv.x, 0.f);
        o.y = fmaxf(acc[i][1] + bv.y, 0.f);
        o.z = fmaxf(acc[i][2] + bv.z, 0.f);
        o.w = fmaxf(acc[i][3] + bv.w, 0.f);
        *(float4*)(C + (size_t)gm * 64 + nn) = o;
    }
}

// ---------------------------------------------------------------------------
// Scan chain
// ---------------------------------------------------------------------------
__global__ void scan1_kernel(int n)
{
    __shared__ int sh[1024];
    int t = threadIdx.x, i = blockIdx.x * 1024 + t;
    int v = (i < n) ? g_cnt[i] : 0;
    sh[t] = v;
    __syncthreads();
    #pragma unroll
    for (int off = 1; off < 1024; off <<= 1) {
        int x = (t >= off) ? sh[t - off] : 0;
        __syncthreads();
        sh[t] += x;
        __syncthreads();
    }
    if (i < n) g_incl[i] = sh[t];
    if (t == 1023) g_bsum[blockIdx.x] = sh[t];
}

__global__ void scan2_kernel(int nb)
{
    __shared__ int sh[128];
    int t = threadIdx.x;
    int v = (t < nb) ? g_bsum[t] : 0;
    sh[t] = v;
    __syncthreads();
    #pragma unroll
    for (int off = 1; off < 128; off <<= 1) {
        int x = (t >= off) ? sh[t - off] : 0;
        __syncthreads();
        sh[t] += x;
        __syncthreads();
    }
    g_bsum[t] = sh[t] - v;
    if (t == 0) g_off[0] = 0;
}

__global__ void scan3_kernel(int n)
{
    int i = blockIdx.x * blockDim.x + threadIdx.x;
    if (i >= n) return;
    int total = g_incl[i] + g_bsum[i >> 10];
    g_off[i + 1] = total;
    g_cur[i] = total - g_cnt[i];
}

__global__ void scatter_kernel(const void* __restrict__ esrc,
                               const void* __restrict__ edst,
                               const float* __restrict__ ev, int E)
{
    int e = blockIdx.x * blockDim.x + threadIdx.x;
    if (e >= E) return;
    int src, dst;
    if (g_is64) {
        src = (int)((const long long*)esrc)[e];
        dst = (int)((const long long*)edst)[e];
    } else {
        src = ((const int*)esrc)[e];
        dst = ((const int*)edst)[e];
    }
    int pos = atomicAdd(&g_cur[dst], 1);
    g_csr[pos] = make_int2(src, __float_as_int(ev[e]));
}

// ---------------------------------------------------------------------------
// CSR spmm: 2 rows per warp, float4 per 16-lane half, unroll-4 inner loop.
// ---------------------------------------------------------------------------
__device__ __forceinline__ float4 spmm_row_acc(const float* __restrict__ hin,
                                               int s, int e, int lane16)
{
    float4 acc = make_float4(0.f, 0.f, 0.f, 0.f);
    int i = s;
    for (; i + 3 < e; i += 4) {
        int2 p0 = __ldg(&g_csr[i]);
        int2 p1 = __ldg(&g_csr[i + 1]);
        int2 p2 = __ldg(&g_csr[i + 2]);
        int2 p3 = __ldg(&g_csr[i + 3]);
        float4 h0 = *((const float4*)(hin + (size_t)p0.x * CDIM) + lane16);
        float4 h1 = *((const float4*)(hin + (size_t)p1.x * CDIM) + lane16);
        float4 h2 = *((const float4*)(hin + (size_t)p2.x * CDIM) + lane16);
        float4 h3 = *((const float4*)(hin + (size_t)p3.x * CDIM) + lane16);
        float v0 = __int_as_float(p0.y), v1 = __int_as_float(p1.y);
        float v2 = __int_as_float(p2.y), v3 = __int_as_float(p3.y);
        acc.x += v0 * h0.x + v1 * h1.x + v2 * h2.x + v3 * h3.x;
        acc.y += v0 * h0.y + v1 * h1.y + v2 * h2.y + v3 * h3.y;
        acc.z += v0 * h0.z + v1 * h1.z + v2 * h2.z + v3 * h3.z;
        acc.w += v0 * h0.w + v1 * h1.w + v2 * h2.w + v3 * h3.w;
    }
    for (; i < e; i++) {
        int2 p0 = __ldg(&g_csr[i]);
        float v0 = __int_as_float(p0.y);
        float4 h0 = *((const float4*)(hin + (size_t)p0.x * CDIM) + lane16);
        acc.x += v0 * h0.x; acc.y += v0 * h0.y;
        acc.z += v0 * h0.z; acc.w += v0 * h0.w;
    }
    return acc;
}

__global__ void spmm_csr(const float* __restrict__ hin,
                         float* __restrict__ hout, int n)
{
    int w = (blockIdx.x * blockDim.x + threadIdx.x) >> 5;
    int lane = threadIdx.x & 31;
    int r = w * 2 + (lane >> 4);
    if (r >= n) return;
    int lane16 = lane & 15;
    float4 acc = spmm_row_acc(hin, g_off[r], g_off[r + 1], lane16);
    *((float4*)(hout + (size_t)r * CDIM) + lane16) = acc;
}

// spmm #3 fused with poly
__global__ void spmm_poly(const float* __restrict__ h,
                          const float* __restrict__ t1,
                          const float* __restrict__ t2,
                          float* __restrict__ poly, int n)
{
    int w = (blockIdx.x * blockDim.x + threadIdx.x) >> 5;
    int lane = threadIdx.x & 31;
    int r = w * 2 + (lane >> 4);
    if (r >= n) return;
    int lane16 = lane & 15;
    float4 d = spmm_row_acc(t2, g_off[r], g_off[r + 1], lane16);   // T3 row

    float4 a = *((const float4*)(h  + (size_t)r * CDIM) + lane16);
    float4 b = *((const float4*)(t1 + (size_t)r * CDIM) + lane16);
    float4 c = *((const float4*)(t2 + (size_t)r * CDIM) + lane16);

    float c00 = g_coef[0], c01 = g_coef[1], c02 = g_coef[2], c03 = g_coef[3];
    float c10 = g_coef[4], c11 = g_coef[5], c12 = g_coef[6], c13 = g_coef[7];

    float4 p0, p1;
    p0.x = c00*a.x + c01*b.x + c02*c.x + c03*d.x;
    p0.y = c00*a.y + c01*b.y + c02*c.y + c03*d.y;
    p0.z = c00*a.z + c01*b.z + c02*c.z + c03*d.z;
    p0.w = c00*a.w + c01*b.w + c02*c.w + c03*d.w;
    p1.x = c10*a.x + c11*b.x + c12*c.x + c13*d.x;
    p1.y = c10*a.y + c11*b.y + c12*c.y + c13*d.y;
    p1.z = c10*a.z + c11*b.z + c12*c.z + c13*d.z;
    p1.w = c10*a.w + c11*b.w + c12*c.w + c13*d.w;

    ((float4*)poly)[((size_t)r * 2    ) * 16 + lane16] = p0;
    ((float4*)poly)[((size_t)r * 2 + 1) * 16 + lane16] = p1;
}

// ---------------------------------------------------------------------------
// Mega-tail: per 64-node block (256 threads):
//   xp  = h @ Wx + bWx                      (register tile, never stored)
//   sc  = sum_c tanh((poly@Wb)+bWb+xp)*vc   (shfl-reduced)
//   a   = softmax_F(sc); res = sum_f a_f poly_f
//   y1 = relu(res@W1+b1); y2 = relu(y1@W2+b2); out = y2@W3+b3
// Dynamic smem: As 64x68 | Ws 64x68 | Ps 64x137 | Ss 128 | Sa0/Sa1 64 each.
// ---------------------------------------------------------------------------
#define TAIL_SMEM_FLOATS (64*68 + 64*68 + 64*137 + 128 + 64 + 64)

__global__ void mega_tail(const float* __restrict__ poly,
                          const float* __restrict__ h,
                          const float* __restrict__ Wx,
                          const float* __restrict__ bWx,
                          const float* __restrict__ Wb,
                          const float* __restrict__ bWb,
                          const float* __restrict__ vc,
                          const float* __restrict__ W1,
                          const float* __restrict__ b1,
                          const float* __restrict__ W2,
                          const float* __restrict__ b2,
                          const float* __restrict__ W3,
                          const float* __restrict__ b3,
                          float* __restrict__ out, int nn)
{
    extern __shared__ float sm[];
    float* As  = sm;                 // [k][m] 64x68
    float* Ws  = As + 64 * 68;       // [k][n] 64x68
    float* Ps  = Ws + 64 * 68;       // [k][m2] 64x137 (poly, 128 rows)
    float* Ss  = Ps + 64 * 137;      // 128 scores
    float* Sa0 = Ss + 128;           // 64
    float* Sa1 = Sa0 + 64;           // 64

    const int tid = threadIdx.x;
    const int b0 = blockIdx.x * 64;
    const int tx = tid & 15;
    const int ty = tid >> 4;

    // ---- stage 0: load h rows -> As, Wx -> Ws, poly rows -> Ps ----
    #pragma unroll
    for (int r = 0; r < 4; r++) {
        int i = tid + r * 256;            // 1024 float4 over h tile
        int m = i >> 4, q = i & 15;
        int gn = b0 + m;
        float4 v = make_float4(0.f, 0.f, 0.f, 0.f);
        if (gn < nn) v = *((const float4*)(h + (size_t)gn * 64) + q);
        As[(q * 4 + 0) * 68 + m] = v.x;
        As[(q * 4 + 1) * 68 + m] = v.y;
        As[(q * 4 + 2) * 68 + m] = v.z;
        As[(q * 4 + 3) * 68 + m] = v.w;
    }
    #pragma unroll
    for (int r = 0; r < 4; r++) {
        int i = tid + r * 256;
        int k = i >> 4, nq = (i & 15) * 4;
        float4 v = *(const float4*)(Wx + (size_t)k * 64 + nq);
        Ws[k * 68 + nq]     = v.x; Ws[k * 68 + nq + 1] = v.y;
        Ws[k * 68 + nq + 2] = v.z; Ws[k * 68 + nq + 3] = v.w;
    }
    #pragma unroll
    for (int r = 0; r < 8; r++) {
        int i = tid + r * 256;            // 2048 float4 over poly 128 rows
        int m = i >> 4, q = i & 15;
        int gr = 2 * b0 + m;
        float4 v = make_float4(0.f, 0.f, 0.f, 0.f);
        if ((gr >> 1) < nn) v = ((const float4*)poly)[(size_t)gr * 16 + q];
        Ps[(q * 4 + 0) * 137 + m] = v.x;
        Ps[(q * 4 + 1) * 137 + m] = v.y;
        Ps[(q * 4 + 2) * 137 + m] = v.z;
        Ps[(q * 4 + 3) * 137 + m] = v.w;
    }
    __syncthreads();

    // ---- stage 1: xp = h @ Wx + bWx (register 4x4, rows=nodes ty*4+i) ----
    float xp[4][4] = {};
    #pragma unroll
    for (int kk = 0; kk < 64; kk++) {
        float4 a = *(const float4*)&As[kk * 68 + ty * 4];
        float4 b = *(const float4*)&Ws[kk * 68 + tx * 4];
        float am[4] = {a.x, a.y, a.z, a.w};
        float bn[4] = {b.x, b.y, b.z, b.w};
        #pragma unroll
        for (int i = 0; i < 4; i++)
            #pragma unroll
            for (int j = 0; j < 4; j++)
                xp[i][j] += am[i] * bn[j];
    }
    {
        float4 bx = *(const float4*)(bWx + tx * 4);
        #pragma unroll
        for (int i = 0; i < 4; i++) {
            xp[i][0] += bx.x; xp[i][1] += bx.y;
            xp[i][2] += bx.z; xp[i][3] += bx.w;
        }
    }
    __syncthreads();

    // load Wb -> Ws
    #pragma unroll
    for (int r = 0; r < 4; r++) {
        int i = tid + r * 256;
        int k = i >> 4, nq = (i & 15) * 4;
        float4 v = *(const float4*)(Wb + (size_t)k * 64 + nq);
        Ws[k * 68 + nq]     = v.x; Ws[k * 68 + nq + 1] = v.y;
        Ws[k * 68 + nq + 2] = v.z; Ws[k * 68 + nq + 3] = v.w;
    }
    __syncthreads();

    // ---- stage 2: scores. rows r=ty*8+i (node ty*4+(i>>1), filter i&1) ----
    {
        float acc2[8][4] = {};
        #pragma unroll
        for (int kk = 0; kk < 64; kk++) {
            float4 b = *(const float4*)&Ws[kk * 68 + tx * 4];
            float bn[4] = {b.x, b.y, b.z, b.w};
            const float* pr = &Ps[kk * 137 + ty * 8];
            #pragma unroll
            for (int i = 0; i < 8; i++) {
                float av = pr[i];
                acc2[i][0] += av * bn[0];
                acc2[i][1] += av * bn[1];
                acc2[i][2] += av * bn[2];
                acc2[i][3] += av * bn[3];
            }
        }
        float4 bb = *(const float4*)(bWb + tx * 4);
        float4 vv = *(const float4*)(vc + tx * 4);
        #pragma unroll
        for (int i = 0; i < 8; i++) {
            int h2 = i >> 1;
            float part;
            part  = tanhf(acc2[i][0] + bb.x + xp[h2][0]) * vv.x;
            part += tanhf(acc2[i][1] + bb.y + xp[h2][1]) * vv.y;
            part += tanhf(acc2[i][2] + bb.z + xp[h2][2]) * vv.z;
            part += tanhf(acc2[i][3] + bb.w + xp[h2][3]) * vv.w;
            #pragma unroll
            for (int o = 8; o > 0; o >>= 1)
                part += __shfl_xor_sync(0xffffffffu, part, o);
            if (tx == 0) Ss[ty * 8 + i] = part;
        }
    }
    __syncthreads();

    // ---- softmax coefficients per node ----
    if (tid < 64) {
        float s0 = Ss[2 * tid], s1 = Ss[2 * tid + 1];
        float m = fmaxf(s0, s1);
        float e0 = expf(s0 - m), e1 = expf(s1 - m);
        float inv = 1.f / (e0 + e1);
        Sa0[tid] = e0 * inv;
        Sa1[tid] = e1 * inv;
    }
    __syncthreads();

    // ---- stage 3: res -> As (reuse), W1 -> Ws (reuse) ----
    #pragma unroll
    for (int r = 0; r < 16; r++) {
        int i = tid + r * 256;            // 4096 = 64ch x 64 nodes
        int c = i >> 6, m = i & 63;
        As[c * 68 + m] = Sa0[m] * Ps[c * 137 + 2 * m]
                       + Sa1[m] * Ps[c * 137 + 2 * m + 1];
    }
    #pragma unroll
    for (int r = 0; r < 4; r++) {
        int i = tid + r * 256;
        int k = i >> 4, nq = (i & 15) * 4;
        float4 v = *(const float4*)(W1 + (size_t)k * 64 + nq);
        Ws[k * 68 + nq]     = v.x; Ws[k * 68 + nq + 1] = v.y;
        Ws[k * 68 + nq + 2] = v.z; Ws[k * 68 + nq + 3] = v.w;
    }
    __syncthreads();

    // ---- stage 4: y1 = relu(res @ W1 + b1) ----
    float acc[4][4] = {};
    #pragma unroll
    for (int kk = 0; kk < 64; kk++) {
        float4 a = *(const float4*)&As[kk * 68 + ty * 4];
        float4 b = *(const float4*)&Ws[kk * 68 + tx * 4];
        float am[4] = {a.x, a.y, a.z, a.w};
        float bn[4] = {b.x, b.y, b.z, b.w};
        #pragma unroll
        for (int i = 0; i < 4; i++)
            #pragma unroll
            for (int j = 0; j < 4; j++)
                acc[i][j] += am[i] * bn[j];
    }
    __syncthreads();

    // write y1^T -> As; W2 -> Ws
    {
        float4 bv = *(const float4*)(b1 + tx * 4);
        float bbv[4] = {bv.x, bv.y, bv.z, bv.w};
        #pragma unroll
        for (int i = 0; i < 4; i++)
            #pragma unroll
            for (int j = 0; j < 4; j++)
                As[(tx * 4 + j) * 68 + ty * 4 + i] = fmaxf(acc[i][j] + bbv[j], 0.f);
    }
    #pragma unroll
    for (int r = 0; r < 2; r++) {
        int i = tid + r * 256;            // 512 float4 = 64x32
        int k = i >> 3, nq = (i & 7) * 4;
        float4 v = *(const float4*)(W2 + (size_t)k * 32 + nq);
        Ws[k * 68 + nq]     = v.x; Ws[k * 68 + nq + 1] = v.y;
        Ws[k * 68 + nq + 2] = v.z; Ws[k * 68 + nq + 3] = v.w;
    }
    __syncthreads();

    // ---- stage 5: y2 = relu(y1@W2+b2); out = y2@W3+b3 ----
    const int tx2 = tid & 15;
    const int ty2 = tid >> 4;
    float acc3[4][2] = {};
    #pragma unroll
    for (int kk = 0; kk < 64; kk++) {
        float4 a = *(const float4*)&As[kk * 68 + ty2 * 4];
        float b0v = Ws[kk * 68 + tx2 * 2];
        float b1v = Ws[kk * 68 + tx2 * 2 + 1];
        float am[4] = {a.x, a.y, a.z, a.w};
        #pragma unroll
        for (int i = 0; i < 4; i++) {
            acc3[i][0] += am[i] * b0v;
            acc3[i][1] += am[i] * b1v;
        }
    }
    float bb0 = b2[tx2 * 2], bb1 = b2[tx2 * 2 + 1];
    float w00 = W3[(tx2 * 2) * 2],     w01 = W3[(tx2 * 2) * 2 + 1];
    float w10 = W3[(tx2 * 2 + 1) * 2], w11 = W3[(tx2 * 2 + 1) * 2 + 1];

    #pragma unroll
    for (int i = 0; i < 4; i++) {
        float y0 = fmaxf(acc3[i][0] + bb0, 0.f);
        float y1v = fmaxf(acc3[i][1] + bb1, 0.f);
        float s0 = y0 * w00 + y1v * w10;
        float s1 = y0 * w01 + y1v * w11;
        #pragma unroll
        for (int o = 8; o > 0; o >>= 1) {
            s0 += __shfl_xor_sync(0xffffffffu, s0, o);
            s1 += __shfl_xor_sync(0xffffffffu, s1, o);
        }
        int gm = b0 + ty2 * 4 + i;
        if (tx2 == 0 && gm < nn) {
            out[gm * 2]     = s0 + b3[0];
            out[gm * 2 + 1] = s1 + b3[1];
        }
    }
}

// ---------------------------------------------------------------------------
extern "C" void kernel_launch(void* const* d_in, const int* in_sizes, int n_in,
                              void* d_out, int out_size)
{
    const float* x      = (const float*)d_in[0];
    const void*  esrc   = d_in[1];
    const void*  edst   = d_in[2];
    const float* ev     = (const float*)d_in[3];
    const float* Win    = (const float*)d_in[4];
    const float* bin    = (const float*)d_in[5];
    const float* thetas = (const float*)d_in[6];
    const float* Wb     = (const float*)d_in[7];
    const float* bWb    = (const float*)d_in[8];
    const float* Wx     = (const float*)d_in[9];
    const float* bWx    = (const float*)d_in[10];
    const float* vc     = (const float*)d_in[11];
    const float* W1     = (const float*)d_in[12];
    const float* b1     = (const float*)d_in[13];
    const float* W2     = (const float*)d_in[14];
    const float* b2     = (const float*)d_in[15];
    const float* W3     = (const float*)d_in[16];
    const float* b3     = (const float*)d_in[17];

    int n = in_sizes[0] / 128;
    int E = in_sizes[3];

    float *ph, *pT1, *pT2, *ppoly;
    int* pcnt;
    cudaGetSymbolAddress((void**)&ph,    g_h);
    cudaGetSymbolAddress((void**)&pT1,   g_T1);
    cudaGetSymbolAddress((void**)&pT2,   g_T2);
    cudaGetSymbolAddress((void**)&ppoly, g_poly);
    cudaGetSymbolAddress((void**)&pcnt,  g_cnt);

    static int smem_set = 0;
    const int tail_smem = TAIL_SMEM_FLOATS * (int)sizeof(float);
    if (!smem_set) {
        cudaFuncSetAttribute(mega_tail,
                             cudaFuncAttributeMaxDynamicSharedMemorySize,
                             tail_smem);
        smem_set = 1;
    }

    prep_kernel<<<1, 32>>>(esrc, thetas);
    cudaMemsetAsync(pcnt, 0, n * sizeof(int), 0);

    // ---- h = relu(x@W_in+b_in)  ||  edge-dst histogram ----
    int GB = (n + 127) / 128;
    int CB = (E + 255) / 256;
    gemm_count<<<GB + CB, 256>>>(x, Win, bin, ph, n, edst, E, GB);

    // ---- scan + scatter ----
    int nb = (n + 1023) / 1024;
    scan1_kernel<<<nb, 1024>>>(n);
    scan2_kernel<<<1, 128>>>(nb);
    scan3_kernel<<<(n + 255) / 256, 256>>>(n);
    scatter_kernel<<<(E + 255) / 256, 256>>>(esrc, edst, ev, E);

    // ---- propagation ----
    int warps = (n + 1) / 2;
    int sb = (warps * 32 + 255) / 256;
    spmm_csr<<<sb, 256>>>(ph,  pT1, n);
    spmm_csr<<<sb, 256>>>(pT1, pT2, n);
    spmm_poly<<<sb, 256>>>(ph, pT1, pT2, ppoly, n);

    // ---- fused attention + MLP ----
    mega_tail<<<(n + 63) / 64, 256, tail_smem>>>(
        ppoly, ph, Wx, bWx, Wb, bWb, vc, W1, b1, W2, b2, W3, b3,
        (float*)d_out, n);
}

// round 5
// speedup vs baseline: 1.8861x; 1.0059x over previous
#include <cuda_runtime.h>
#include <cstdint>

// ---------------------------------------------------------------------------
// NodeBernNet fixed shapes: N=100000, E=1600000, C_IN=128, C=64, F=2, K+1=4.
// R5: poly-spmm fused INTO mega_tail (g_poly eliminated); front-end reorder
// (count -> scan -> [scatter || gemm]); int2 CSR unroll-4 spmm.
// ---------------------------------------------------------------------------

#define NMAX 100000
#define EMAX 1600000
#define CDIM 64

__device__ __align__(256) float g_h [NMAX * CDIM];
__device__ __align__(256) float g_T1[NMAX * CDIM];
__device__ __align__(256) float g_T2[NMAX * CDIM];
// CSR scratch
__device__ int   g_cnt [NMAX];
__device__ int   g_incl[NMAX];
__device__ int   g_bsum[128];
__device__ int   g_off [NMAX + 1];
__device__ int   g_cur [NMAX];
__device__ __align__(16) int2 g_csr[EMAX];   // {src, val bits}

__device__ float g_coef[8];   // thetas @ BCOEF, [F=2][K+1=4]
__device__ int   g_is64;

// ---------------------------------------------------------------------------
__global__ void prep_kernel(const void* __restrict__ esrc,
                            const float* __restrict__ thetas)
{
    if (threadIdx.x == 0) {
        const int* w = (const int*)esrc;
        g_is64 = (w[1] == 0 && w[3] == 0 && w[5] == 0 && w[7] == 0) ? 1 : 0;
        const float B[4][4] = {
            {1.f, -3.f,  3.f, -1.f},
            {0.f,  3.f, -6.f,  3.f},
            {0.f,  0.f,  3.f, -3.f},
            {0.f,  0.f,  0.f,  1.f}};
        for (int f = 0; f < 2; f++)
            for (int k = 0; k < 4; k++) {
                float s = 0.f;
                for (int j = 0; j < 4; j++) s += thetas[f * 4 + j] * B[j][k];
                g_coef[f * 4 + k] = s;
            }
    }
}

// ---------------------------------------------------------------------------
__global__ void count_kernel(const void* __restrict__ edst, int E)
{
    int e = blockIdx.x * blockDim.x + threadIdx.x;
    if (e >= E) return;
    int dst = g_is64 ? (int)((const long long*)edst)[e] : ((const int*)edst)[e];
    atomicAdd(&g_cnt[dst], 1);
}

__global__ void scan1_kernel(int n)
{
    __shared__ int sh[1024];
    int t = threadIdx.x, i = blockIdx.x * 1024 + t;
    int v = (i < n) ? g_cnt[i] : 0;
    sh[t] = v;
    __syncthreads();
    #pragma unroll
    for (int off = 1; off < 1024; off <<= 1) {
        int x = (t >= off) ? sh[t - off] : 0;
        __syncthreads();
        sh[t] += x;
        __syncthreads();
    }
    if (i < n) g_incl[i] = sh[t];
    if (t == 1023) g_bsum[blockIdx.x] = sh[t];
}

__global__ void scan2_kernel(int nb)
{
    __shared__ int sh[128];
    int t = threadIdx.x;
    int v = (t < nb) ? g_bsum[t] : 0;
    sh[t] = v;
    __syncthreads();
    #pragma unroll
    for (int off = 1; off < 128; off <<= 1) {
        int x = (t >= off) ? sh[t - off] : 0;
        __syncthreads();
        sh[t] += x;
        __syncthreads();
    }
    g_bsum[t] = sh[t] - v;
    if (t == 0) g_off[0] = 0;
}

__global__ void scan3_kernel(int n)
{
    int i = blockIdx.x * blockDim.x + threadIdx.x;
    if (i >= n) return;
    int total = g_incl[i] + g_bsum[i >> 10];
    g_off[i + 1] = total;
    g_cur[i] = total - g_cnt[i];
}

// ---------------------------------------------------------------------------
// Fat kernel: blocks [0,GB) do h = relu(x @ W_in + b_in); blocks [GB,GB+SB)
// do the CSR scatter. GEMM blocks first (longer pole).
// ---------------------------------------------------------------------------
__global__ void gemm_scatter(const float* __restrict__ A,
                             const float* __restrict__ W,
                             const float* __restrict__ bias,
                             float* __restrict__ C, int M,
                             const void* __restrict__ esrc,
                             const void* __restrict__ edst,
                             const float* __restrict__ ev, int E, int GB)
{
    if ((int)blockIdx.x >= GB) {
        int e = (blockIdx.x - GB) * blockDim.x + threadIdx.x;
        if (e < E) {
            int src, dst;
            if (g_is64) {
                src = (int)((const long long*)esrc)[e];
                dst = (int)((const long long*)edst)[e];
            } else {
                src = ((const int*)esrc)[e];
                dst = ((const int*)edst)[e];
            }
            int pos = atomicAdd(&g_cur[dst], 1);
            g_csr[pos] = make_int2(src, __float_as_int(ev[e]));
        }
        return;
    }

    __shared__ float As[16][132];
    __shared__ float Bs[16][68];

    const int tid = threadIdx.x;
    const int tx = tid & 15;
    const int ty = tid >> 4;
    const int m0 = blockIdx.x * 128;

    float acc[8][4] = {};

    for (int k0 = 0; k0 < 128; k0 += 16) {
        #pragma unroll
        for (int r = 0; r < 2; r++) {
            int i = tid + r * 256;
            int row = i >> 2, kq = i & 3;
            int gm = m0 + row;
            float4 v = make_float4(0.f, 0.f, 0.f, 0.f);
            if (gm < M) v = *(const float4*)(A + (size_t)gm * 128 + k0 + kq * 4);
            As[kq * 4 + 0][row] = v.x;
            As[kq * 4 + 1][row] = v.y;
            As[kq * 4 + 2][row] = v.z;
            As[kq * 4 + 3][row] = v.w;
        }
        {
            int k = tid >> 4, nn = (tid & 15) * 4;
            float4 v = *(const float4*)(W + (size_t)(k0 + k) * 64 + nn);
            Bs[k][nn + 0] = v.x; Bs[k][nn + 1] = v.y;
            Bs[k][nn + 2] = v.z; Bs[k][nn + 3] = v.w;
        }
        __syncthreads();
        #pragma unroll
        for (int kk = 0; kk < 16; kk++) {
            float4 a0 = *(const float4*)&As[kk][ty * 8];
            float4 a1 = *(const float4*)&As[kk][ty * 8 + 4];
            float4 b  = *(const float4*)&Bs[kk][tx * 4];
            float am[8] = {a0.x, a0.y, a0.z, a0.w, a1.x, a1.y, a1.z, a1.w};
            float bn[4] = {b.x, b.y, b.z, b.w};
            #pragma unroll
            for (int i = 0; i < 8; i++)
                #pragma unroll
                for (int j = 0; j < 4; j++)
                    acc[i][j] += am[i] * bn[j];
        }
        __syncthreads();
    }

    int nn = tx * 4;
    float4 bv = *(const float4*)(bias + nn);
    #pragma unroll
    for (int i = 0; i < 8; i++) {
        int gm = m0 + ty * 8 + i;
        if (gm >= M) continue;
        float4 o;
        o.x = fmaxf(acc[i][0] + bv.x, 0.f);
        o.y = fmaxf(acc[i][1] + bv.y, 0.f);
        o.z = fmaxf(acc[i][2] + bv.z, 0.f);
        o.w = fmaxf(acc[i][3] + bv.w, 0.f);
        *(float4*)(C + (size_t)gm * 64 + nn) = o;
    }
}

// ---------------------------------------------------------------------------
// CSR row gather-accumulate: float4 over 16-lane half, unroll-4.
// ---------------------------------------------------------------------------
__device__ __forceinline__ float4 spmm_row_acc(const float* __restrict__ hin,
                                               int s, int e, int lane16)
{
    float4 acc = make_float4(0.f, 0.f, 0.f, 0.f);
    int i = s;
    for (; i + 3 < e; i += 4) {
        int2 p0 = __ldg(&g_csr[i]);
        int2 p1 = __ldg(&g_csr[i + 1]);
        int2 p2 = __ldg(&g_csr[i + 2]);
        int2 p3 = __ldg(&g_csr[i + 3]);
        float4 h0 = *((const float4*)(hin + (size_t)p0.x * CDIM) + lane16);
        float4 h1 = *((const float4*)(hin + (size_t)p1.x * CDIM) + lane16);
        float4 h2 = *((const float4*)(hin + (size_t)p2.x * CDIM) + lane16);
        float4 h3 = *((const float4*)(hin + (size_t)p3.x * CDIM) + lane16);
        float v0 = __int_as_float(p0.y), v1 = __int_as_float(p1.y);
        float v2 = __int_as_float(p2.y), v3 = __int_as_float(p3.y);
        acc.x += v0 * h0.x + v1 * h1.x + v2 * h2.x + v3 * h3.x;
        acc.y += v0 * h0.y + v1 * h1.y + v2 * h2.y + v3 * h3.y;
        acc.z += v0 * h0.z + v1 * h1.z + v2 * h2.z + v3 * h3.z;
        acc.w += v0 * h0.w + v1 * h1.w + v2 * h2.w + v3 * h3.w;
    }
    for (; i < e; i++) {
        int2 p0 = __ldg(&g_csr[i]);
        float v0 = __int_as_float(p0.y);
        float4 h0 = *((const float4*)(hin + (size_t)p0.x * CDIM) + lane16);
        acc.x += v0 * h0.x; acc.y += v0 * h0.y;
        acc.z += v0 * h0.z; acc.w += v0 * h0.w;
    }
    return acc;
}

__global__ void spmm_csr(const float* __restrict__ hin,
                         float* __restrict__ hout, int n)
{
    int w = (blockIdx.x * blockDim.x + threadIdx.x) >> 5;
    int lane = threadIdx.x & 31;
    int r = w * 2 + (lane >> 4);
    if (r >= n) return;
    int lane16 = lane & 15;
    float4 acc = spmm_row_acc(hin, g_off[r], g_off[r + 1], lane16);
    *((float4*)(hout + (size_t)r * CDIM) + lane16) = acc;
}

// ---------------------------------------------------------------------------
// Mega-tail (now includes the 3rd-hop spmm + poly):
//   T3row = gather(T2);  poly -> Ps (smem only, never global)
//   xp  = h @ Wx + bWx      (register tile)
//   sc  = sum_c tanh((poly@Wb)+bWb+xp)*vc
//   a = softmax_F(sc); res = sum_f a_f poly_f
//   y1 = relu(res@W1+b1); y2 = relu(y1@W2+b2); out = y2@W3+b3
// ---------------------------------------------------------------------------
#define TAIL_SMEM_FLOATS (64*68 + 64*68 + 64*137 + 128 + 64 + 64)

__global__ void mega_tail(const float* __restrict__ h,
                          const float* __restrict__ t1,
                          const float* __restrict__ t2,
                          const float* __restrict__ Wx,
                          const float* __restrict__ bWx,
                          const float* __restrict__ Wb,
                          const float* __restrict__ bWb,
                          const float* __restrict__ vc,
                          const float* __restrict__ W1,
                          const float* __restrict__ b1,
                          const float* __restrict__ W2,
                          const float* __restrict__ b2,
                          const float* __restrict__ W3,
                          const float* __restrict__ b3,
                          float* __restrict__ out, int nn)
{
    extern __shared__ float sm[];
    float* As  = sm;                 // [k][m] 64x68
    float* Ws  = As + 64 * 68;       // [k][n] 64x68
    float* Ps  = Ws + 64 * 68;       // [c][row] 64x137 (poly, 128 rows)
    float* Ss  = Ps + 64 * 137;      // 128 scores
    float* Sa0 = Ss + 128;
    float* Sa1 = Sa0 + 64;

    const int tid = threadIdx.x;
    const int b0 = blockIdx.x * 64;
    const int tx = tid & 15;
    const int ty = tid >> 4;

    // ---- loaders: h rows -> As (transposed), Wx -> Ws ----
    #pragma unroll
    for (int r = 0; r < 4; r++) {
        int i = tid + r * 256;
        int m = i >> 4, q = i & 15;
        int gn = b0 + m;
        float4 v = make_float4(0.f, 0.f, 0.f, 0.f);
        if (gn < nn) v = *((const float4*)(h + (size_t)gn * 64) + q);
        As[(q * 4 + 0) * 68 + m] = v.x;
        As[(q * 4 + 1) * 68 + m] = v.y;
        As[(q * 4 + 2) * 68 + m] = v.z;
        As[(q * 4 + 3) * 68 + m] = v.w;
    }
    #pragma unroll
    for (int r = 0; r < 4; r++) {
        int i = tid + r * 256;
        int k = i >> 4, nq = (i & 15) * 4;
        float4 v = *(const float4*)(Wx + (size_t)k * 64 + nq);
        Ws[k * 68 + nq]     = v.x; Ws[k * 68 + nq + 1] = v.y;
        Ws[k * 68 + nq + 2] = v.z; Ws[k * 68 + nq + 3] = v.w;
    }

    // ---- stage A: 3rd-hop spmm + poly for this block's 64 nodes -> Ps ----
    {
        int wid = tid >> 5;
        int lane = tid & 31;
        int lane16 = lane & 15;
        float c00 = g_coef[0], c01 = g_coef[1], c02 = g_coef[2], c03 = g_coef[3];
        float c10 = g_coef[4], c11 = g_coef[5], c12 = g_coef[6], c13 = g_coef[7];
        #pragma unroll
        for (int it = 0; it < 4; it++) {
            int local = wid * 8 + it * 2 + (lane >> 4);
            int r = b0 + local;
            float4 p0 = make_float4(0.f, 0.f, 0.f, 0.f);
            float4 p1 = make_float4(0.f, 0.f, 0.f, 0.f);
            if (r < nn) {
                float4 d = spmm_row_acc(t2, g_off[r], g_off[r + 1], lane16);
                float4 a = *((const float4*)(h  + (size_t)r * CDIM) + lane16);
                float4 b = *((const float4*)(t1 + (size_t)r * CDIM) + lane16);
                float4 c = *((const float4*)(t2 + (size_t)r * CDIM) + lane16);
                p0.x = c00*a.x + c01*b.x + c02*c.x + c03*d.x;
                p0.y = c00*a.y + c01*b.y + c02*c.y + c03*d.y;
                p0.z = c00*a.z + c01*b.z + c02*c.z + c03*d.z;
                p0.w = c00*a.w + c01*b.w + c02*c.w + c03*d.w;
                p1.x = c10*a.x + c11*b.x + c12*c.x + c13*d.x;
                p1.y = c10*a.y + c11*b.y + c12*c.y + c13*d.y;
                p1.z = c10*a.z + c11*b.z + c12*c.z + c13*d.z;
                p1.w = c10*a.w + c11*b.w + c12*c.w + c13*d.w;
            }
            int cb = lane16 * 4;
            int m2 = 2 * local;
            Ps[(cb + 0) * 137 + m2] = p0.x; Ps[(cb + 0) * 137 + m2 + 1] = p1.x;
            Ps[(cb + 1) * 137 + m2] = p0.y; Ps[(cb + 1) * 137 + m2 + 1] = p1.y;
            Ps[(cb + 2) * 137 + m2] = p0.z; Ps[(cb + 2) * 137 + m2 + 1] = p1.z;
            Ps[(cb + 3) * 137 + m2] = p0.w; Ps[(cb + 3) * 137 + m2 + 1] = p1.w;
        }
    }
    __syncthreads();

    // ---- stage 1: xp = h @ Wx + bWx (register 4x4) ----
    float xp[4][4] = {};
    #pragma unroll
    for (int kk = 0; kk < 64; kk++) {
        float4 a = *(const float4*)&As[kk * 68 + ty * 4];
        float4 b = *(const float4*)&Ws[kk * 68 + tx * 4];
        float am[4] = {a.x, a.y, a.z, a.w};
        float bn[4] = {b.x, b.y, b.z, b.w};
        #pragma unroll
        for (int i = 0; i < 4; i++)
            #pragma unroll
            for (int j = 0; j < 4; j++)
                xp[i][j] += am[i] * bn[j];
    }
    {
        float4 bx = *(const float4*)(bWx + tx * 4);
        #pragma unroll
        for (int i = 0; i < 4; i++) {
            xp[i][0] += bx.x; xp[i][1] += bx.y;
            xp[i][2] += bx.z; xp[i][3] += bx.w;
        }
    }
    __syncthreads();

    // load Wb -> Ws
    #pragma unroll
    for (int r = 0; r < 4; r++) {
        int i = tid + r * 256;
        int k = i >> 4, nq = (i & 15) * 4;
        float4 v = *(const float4*)(Wb + (size_t)k * 64 + nq);
        Ws[k * 68 + nq]     = v.x; Ws[k * 68 + nq + 1] = v.y;
        Ws[k * 68 + nq + 2] = v.z; Ws[k * 68 + nq + 3] = v.w;
    }
    __syncthreads();

    // ---- stage 2: scores (rows r=ty*8+i: node ty*4+(i>>1), filter i&1) ----
    {
        float acc2[8][4] = {};
        #pragma unroll
        for (int kk = 0; kk < 64; kk++) {
            float4 b = *(const float4*)&Ws[kk * 68 + tx * 4];
            float bn[4] = {b.x, b.y, b.z, b.w};
            const float* pr = &Ps[kk * 137 + ty * 8];
            #pragma unroll
            for (int i = 0; i < 8; i++) {
                float av = pr[i];
                acc2[i][0] += av * bn[0];
                acc2[i][1] += av * bn[1];
                acc2[i][2] += av * bn[2];
                acc2[i][3] += av * bn[3];
            }
        }
        float4 bb = *(const float4*)(bWb + tx * 4);
        float4 vv = *(const float4*)(vc + tx * 4);
        #pragma unroll
        for (int i = 0; i < 8; i++) {
            int h2 = i >> 1;
            float part;
            part  = tanhf(acc2[i][0] + bb.x + xp[h2][0]) * vv.x;
            part += tanhf(acc2[i][1] + bb.y + xp[h2][1]) * vv.y;
            part += tanhf(acc2[i][2] + bb.z + xp[h2][2]) * vv.z;
            part += tanhf(acc2[i][3] + bb.w + xp[h2][3]) * vv.w;
            #pragma unroll
            for (int o = 8; o > 0; o >>= 1)
                part += __shfl_xor_sync(0xffffffffu, part, o);
            if (tx == 0) Ss[ty * 8 + i] = part;
        }
    }
    __syncthreads();

    // ---- softmax coefficients per node ----
    if (tid < 64) {
        float s0 = Ss[2 * tid], s1 = Ss[2 * tid + 1];
        float m = fmaxf(s0, s1);
        float e0 = expf(s0 - m), e1 = expf(s1 - m);
        float inv = 1.f / (e0 + e1);
        Sa0[tid] = e0 * inv;
        Sa1[tid] = e1 * inv;
    }
    __syncthreads();

    // ---- stage 3: res -> As, W1 -> Ws ----
    #pragma unroll
    for (int r = 0; r < 16; r++) {
        int i = tid + r * 256;
        int c = i >> 6, m = i & 63;
        As[c * 68 + m] = Sa0[m] * Ps[c * 137 + 2 * m]
                       + Sa1[m] * Ps[c * 137 + 2 * m + 1];
    }
    #pragma unroll
    for (int r = 0; r < 4; r++) {
        int i = tid + r * 256;
        int k = i >> 4, nq = (i & 15) * 4;
        float4 v = *(const float4*)(W1 + (size_t)k * 64 + nq);
        Ws[k * 68 + nq]     = v.x; Ws[k * 68 + nq + 1] = v.y;
        Ws[k * 68 + nq + 2] = v.z; Ws[k * 68 + nq + 3] = v.w;
    }
    __syncthreads();

    // ---- stage 4: y1 = relu(res @ W1 + b1) ----
    float acc[4][4] = {};
    #pragma unroll
    for (int kk = 0; kk < 64; kk++) {
        float4 a = *(const float4*)&As[kk * 68 + ty * 4];
        float4 b = *(const float4*)&Ws[kk * 68 + tx * 4];
        float am[4] = {a.x, a.y, a.z, a.w};
        float bn[4] = {b.x, b.y, b.z, b.w};
        #pragma unroll
        for (int i = 0; i < 4; i++)
            #pragma unroll
            for (int j = 0; j < 4; j++)
                acc[i][j] += am[i] * bn[j];
    }
    __syncthreads();

    // write y1^T -> As; W2 -> Ws
    {
        float4 bv = *(const float4*)(b1 + tx * 4);
        float bbv[4] = {bv.x, bv.y, bv.z, bv.w};
        #pragma unroll
        for (int i = 0; i < 4; i++)
            #pragma unroll
            for (int j = 0; j < 4; j++)
                As[(tx * 4 + j) * 68 + ty * 4 + i] = fmaxf(acc[i][j] + bbv[j], 0.f);
    }
    #pragma unroll
    for (int r = 0; r < 2; r++) {
        int i = tid + r * 256;
        int k = i >> 3, nq = (i & 7) * 4;
        float4 v = *(const float4*)(W2 + (size_t)k * 32 + nq);
        Ws[k * 68 + nq]     = v.x; Ws[k * 68 + nq + 1] = v.y;
        Ws[k * 68 + nq + 2] = v.z; Ws[k * 68 + nq + 3] = v.w;
    }
    __syncthreads();

    // ---- stage 5: y2 = relu(y1@W2+b2); out = y2@W3+b3 ----
    const int tx2 = tid & 15;
    const int ty2 = tid >> 4;
    float acc3[4][2] = {};
    #pragma unroll
    for (int kk = 0; kk < 64; kk++) {
        float4 a = *(const float4*)&As[kk * 68 + ty2 * 4];
        float b0v = Ws[kk * 68 + tx2 * 2];
        float b1v = Ws[kk * 68 + tx2 * 2 + 1];
        float am[4] = {a.x, a.y, a.z, a.w};
        #pragma unroll
        for (int i = 0; i < 4; i++) {
            acc3[i][0] += am[i] * b0v;
            acc3[i][1] += am[i] * b1v;
        }
    }
    float bb0 = b2[tx2 * 2], bb1 = b2[tx2 * 2 + 1];
    float w00 = W3[(tx2 * 2) * 2],     w01 = W3[(tx2 * 2) * 2 + 1];
    float w10 = W3[(tx2 * 2 + 1) * 2], w11 = W3[(tx2 * 2 + 1) * 2 + 1];

    #pragma unroll
    for (int i = 0; i < 4; i++) {
        float y0 = fmaxf(acc3[i][0] + bb0, 0.f);
        float y1v = fmaxf(acc3[i][1] + bb1, 0.f);
        float s0 = y0 * w00 + y1v * w10;
        float s1 = y0 * w01 + y1v * w11;
        #pragma unroll
        for (int o = 8; o > 0; o >>= 1) {
            s0 += __shfl_xor_sync(0xffffffffu, s0, o);
            s1 += __shfl_xor_sync(0xffffffffu, s1, o);
        }
        int gm = b0 + ty2 * 4 + i;
        if (tx2 == 0 && gm < nn) {
            out[gm * 2]     = s0 + b3[0];
            out[gm * 2 + 1] = s1 + b3[1];
        }
    }
}

// ---------------------------------------------------------------------------
extern "C" void kernel_launch(void* const* d_in, const int* in_sizes, int n_in,
                              void* d_out, int out_size)
{
    const float* x      = (const float*)d_in[0];
    const void*  esrc   = d_in[1];
    const void*  edst   = d_in[2];
    const float* ev     = (const float*)d_in[3];
    const float* Win    = (const float*)d_in[4];
    const float* bin    = (const float*)d_in[5];
    const float* thetas = (const float*)d_in[6];
    const float* Wb     = (const float*)d_in[7];
    const float* bWb    = (const float*)d_in[8];
    const float* Wx     = (const float*)d_in[9];
    const float* bWx    = (const float*)d_in[10];
    const float* vc     = (const float*)d_in[11];
    const float* W1     = (const float*)d_in[12];
    const float* b1     = (const float*)d_in[13];
    const float* W2     = (const float*)d_in[14];
    const float* b2     = (const float*)d_in[15];
    const float* W3     = (const float*)d_in[16];
    const float* b3     = (const float*)d_in[17];

    int n = in_sizes[0] / 128;
    int E = in_sizes[3];

    float *ph, *pT1, *pT2;
    int* pcnt;
    cudaGetSymbolAddress((void**)&ph,   g_h);
    cudaGetSymbolAddress((void**)&pT1,  g_T1);
    cudaGetSymbolAddress((void**)&pT2,  g_T2);
    cudaGetSymbolAddress((void**)&pcnt, g_cnt);

    static int smem_set = 0;
    const int tail_smem = TAIL_SMEM_FLOATS * (int)sizeof(float);
    if (!smem_set) {
        cudaFuncSetAttribute(mega_tail,
                             cudaFuncAttributeMaxDynamicSharedMemorySize,
                             tail_smem);
        smem_set = 1;
    }

    cudaMemsetAsync(pcnt, 0, n * sizeof(int), 0);
    prep_kernel<<<1, 32>>>(esrc, thetas);

    // ---- CSR count + scan ----
    count_kernel<<<(E + 255) / 256, 256>>>(edst, E);
    int nb = (n + 1023) / 1024;
    scan1_kernel<<<nb, 1024>>>(n);
    scan2_kernel<<<1, 128>>>(nb);
    scan3_kernel<<<(n + 255) / 256, 256>>>(n);

    // ---- [h = relu(x@W_in+b_in)] || [CSR scatter] ----
    int GB = (n + 127) / 128;
    int SB = (E + 255) / 256;
    gemm_scatter<<<GB + SB, 256>>>(x, Win, bin, ph, n, esrc, edst, ev, E, GB);

    // ---- hops 1 and 2 ----
    int warps = (n + 1) / 2;
    int sb = (warps * 32 + 255) / 256;
    spmm_csr<<<sb, 256>>>(ph,  pT1, n);
    spmm_csr<<<sb, 256>>>(pT1, pT2, n);

    // ---- fused hop-3 + poly + attention + MLP ----
    mega_tail<<<(n + 63) / 64, 256, tail_smem>>>(
        ph, pT1, pT2, Wx, bWx, Wb, bWb, vc, W1, b1, W2, b2, W3, b3,
        (float*)d_out, n);
}